// round 10
// baseline (speedup 1.0000x reference)
#include <cuda_runtime.h>
#include <cuda_bf16.h>
#include <math.h>
#include <stdint.h>

// ---------------- problem constants ----------------
#define BATCH   8
#define SEQ     2048
#define DMODEL  1024
#define FFDIM   4096
#define NCAT    75
#define D3      512
#define VOCAB   32000
#define TOK     (BATCH*SEQ)    // 16384

// ---------------- arena (all offsets in MiB) ----------------
#define MB (1ull<<20)
#define OFF_X_F    (0ull*MB)     // [16384,1024] f32
#define OFF_K_F    (64ull*MB)
#define OFF_V_F    (128ull*MB)
#define OFF_U_F    (192ull*MB)
#define OFF_H1_F   (256ull*MB)
#define OFF_FFO_F  (320ull*MB)
#define OFF_H2_F   (384ull*MB)
#define OFF_T3_F   (448ull*MB)   // [16384,512] f32
#define OFF_XH     (480ull*MB)   // bf16 [16384,1024]
#define OFF_XL     (512ull*MB)
#define OFF_QH     (544ull*MB)
#define OFF_QL     (576ull*MB)
#define OFF_KTH    (608ull*MB)   // bf16 [8][1024,2048]
#define OFF_KTL    (640ull*MB)
#define OFF_VTH    (672ull*MB)
#define OFF_VTL    (704ull*MB)
#define OFF_KVH    (736ull*MB)   // bf16 [8][1024,1024]
#define OFF_KVL    (752ull*MB)
#define OFF_AH     (768ull*MB)
#define OFF_AL     (800ull*MB)
#define OFF_H1H    (832ull*MB)
#define OFF_H1L    (864ull*MB)
#define OFF_FBH    (896ull*MB)   // bf16 [16384,4096]
#define OFF_FBL    (1024ull*MB)
#define OFF_H2H    (1152ull*MB)
#define OFF_H2L    (1184ull*MB)
#define OFF_WQTH   (1216ull*MB)
#define OFF_WQTL   (1218ull*MB)
#define OFF_WKTH   (1220ull*MB)
#define OFF_WKTL   (1222ull*MB)
#define OFF_WVTH   (1224ull*MB)
#define OFF_WVTL   (1226ull*MB)
#define OFF_WUTH   (1228ull*MB)
#define OFF_WUTL   (1230ull*MB)
#define OFF_W1TH   (1232ull*MB)  // [4096,1024] bf16
#define OFF_W1TL   (1240ull*MB)
#define OFF_W2TH   (1248ull*MB)  // [1024,4096] bf16
#define OFF_W2TL   (1256ull*MB)
#define OFF_W3TH   (1264ull*MB)  // [512,1024] bf16
#define OFF_W3TL   (1265ull*MB)
#define ARENA_BYTES (1266ull*MB)

__device__ __align__(1024) unsigned char g_arena[ARENA_BYTES];

// ---------------- PTX helpers (sm_80-class only: cp.async / ldmatrix / mma) ----------------
__device__ __forceinline__ uint32_t smem_u32(const void* p) {
    uint32_t a;
    asm("{ .reg .u64 t; cvta.to.shared.u64 t, %1; cvt.u32.u64 %0, t; }" : "=r"(a) : "l"(p));
    return a;
}
__device__ __forceinline__ void cp16(uint32_t s, const void* g) {
    asm volatile("cp.async.cg.shared.global [%0], [%1], 16;" :: "r"(s), "l"(g));
}
#define CP_COMMIT() asm volatile("cp.async.commit_group;" ::: "memory")
#define CP_WAIT1()  asm volatile("cp.async.wait_group 1;"  ::: "memory")

#define LDSM_X4(R, addr) \
    asm volatile("ldmatrix.sync.aligned.m8n8.x4.shared.b16 {%0,%1,%2,%3}, [%4];" \
        : "=r"((R)[0]), "=r"((R)[1]), "=r"((R)[2]), "=r"((R)[3]) : "r"(addr))

#define MMA16816(ac, A, B0, B1) \
    asm volatile("mma.sync.aligned.m16n8k16.row.col.f32.bf16.bf16.f32 " \
        "{%0,%1,%2,%3},{%4,%5,%6,%7},{%8,%9},{%0,%1,%2,%3};" \
        : "+f"((ac)[0]), "+f"((ac)[1]), "+f"((ac)[2]), "+f"((ac)[3]) \
        : "r"((A)[0]), "r"((A)[1]), "r"((A)[2]), "r"((A)[3]), "r"(B0), "r"(B1))

// ---------------- bf16 hi/lo mma.sync GEMM ----------------
// C[M,N] = alpha * (A @ B^T) (+bias) (opt relu)
// A: [M,K] bf16 hi/lo K-major rows; B: [N,K] bf16 hi/lo K-major rows.
// Tile: BM=256, BN=128, BK=64. 16 warps = 8(m) x 2(n), warp tile 32x64.
// 2-stage cp.async pipeline (2 x 96KB). SW128 swizzle per 8-row block.
#define BM 256
#define BN 128
#define BK 64
#define NTHREAD 512
#define STAGE_BYTES 98304      // Ah 32K | Al 32K | Bh 16K | Bl 16K
#define NSTAGE 2
#define GSMEM_BYTES (NSTAGE*STAGE_BYTES)

template<int RELU, int HAS_BIAS, int WF32, int WBF16>
__global__ __launch_bounds__(NTHREAD, 1)
void gemm_mma(const __nv_bfloat16* __restrict__ Ah, const __nv_bfloat16* __restrict__ Al,
              const __nv_bfloat16* __restrict__ Bh, const __nv_bfloat16* __restrict__ Bl,
              const float* __restrict__ bias,
              float* __restrict__ Cf, __nv_bfloat16* __restrict__ Ch,
              __nv_bfloat16* __restrict__ Cl,
              int Kd, int ldc, float alpha,
              long long sA, long long sB, long long sC)
{
    extern __shared__ char smc[];
    const int tid  = threadIdx.x;
    const int wid  = tid >> 5;
    const int lane = tid & 31;
    const int bm   = blockIdx.y * BM;
    const int bn   = blockIdx.x * BN;
    const size_t z = blockIdx.z;

    const char* gAh = (const char*)(Ah + z * sA + (size_t)bm * Kd);
    const char* gAl = (const char*)(Al + z * sA + (size_t)bm * Kd);
    const char* gBh = (const char*)(Bh + z * sB + (size_t)bn * Kd);
    const char* gBl = (const char*)(Bl + z * sB + (size_t)bn * Kd);

    const uint32_t sb = smem_u32(smc);
    const size_t Kb = (size_t)Kd * 2;      // row stride in bytes

    const int ck = tid & 7;                // k-chunk (16B) within row

    auto issue = [&](int s, uint32_t sbase) {
        const size_t kof = (size_t)s * (BK * 2) + (size_t)ck * 16;
        // A: 256 rows, 4 per thread
#pragma unroll
        for (int j = 0; j < 4; j++) {
            const int row = (tid + j * NTHREAD) >> 3;
            const size_t go = (size_t)row * Kb + kof;
            const uint32_t so = row * 128 + ((ck * 16) ^ ((row & 7) * 16));
            cp16(sbase + so,         gAh + go);
            cp16(sbase + 32768 + so, gAl + go);
        }
        // B: 128 rows, 2 per thread
#pragma unroll
        for (int j = 0; j < 2; j++) {
            const int row = (tid + j * NTHREAD) >> 3;
            const size_t go = (size_t)row * Kb + kof;
            const uint32_t so = row * 128 + ((ck * 16) ^ ((row & 7) * 16));
            cp16(sbase + 65536 + so, gBh + go);
            cp16(sbase + 81920 + so, gBl + go);
        }
        CP_COMMIT();
    };

    const int nstg = Kd / BK;
    issue(0, sb);
    issue(1, sb + STAGE_BYTES);

    const int wm = wid & 7, wn = wid >> 3;
    const int mArow = wm * 32 + (lane & 15);
    const int aKh   = lane >> 4;                       // k-half for A ldmatrix
    const int bNrow = wn * 64 + (lane & 7) + ((lane >> 4) << 3);
    const int bKh   = (lane >> 3) & 1;                 // k-half for B ldmatrix

    float acc[2][8][4];
#pragma unroll
    for (int i = 0; i < 2; i++)
#pragma unroll
        for (int j = 0; j < 8; j++)
#pragma unroll
            for (int q = 0; q < 4; q++) acc[i][j][q] = 0.0f;

#pragma unroll 1
    for (int i = 0; i < nstg; i++) {
        CP_WAIT1();
        __syncthreads();
        const uint32_t base = sb + (uint32_t)(i & 1) * STAGE_BYTES;

#pragma unroll
        for (int ks = 0; ks < 4; ks++) {
            const uint32_t kb_a = ks * 32 + aKh * 16;
            const uint32_t kb_b = ks * 32 + bKh * 16;
            uint32_t a_h[2][4], a_l[2][4];
#pragma unroll
            for (int mf = 0; mf < 2; mf++) {
                const int m = mArow + mf * 16;
                const uint32_t so = m * 128 + (kb_a ^ ((m & 7) * 16));
                LDSM_X4(a_h[mf], base + so);
                LDSM_X4(a_l[mf], base + 32768 + so);
            }
#pragma unroll
            for (int nt = 0; nt < 4; nt++) {
                const int n = bNrow + nt * 16;
                const uint32_t so = n * 128 + (kb_b ^ ((n & 7) * 16));
                uint32_t b_h[4], b_l[4];
                LDSM_X4(b_h, base + 65536 + so);
                LDSM_X4(b_l, base + 81920 + so);
#pragma unroll
                for (int mf = 0; mf < 2; mf++) {
                    MMA16816(acc[mf][nt*2],   a_h[mf], b_h[0], b_h[1]);
                    MMA16816(acc[mf][nt*2+1], a_h[mf], b_h[2], b_h[3]);
                    MMA16816(acc[mf][nt*2],   a_h[mf], b_l[0], b_l[1]);
                    MMA16816(acc[mf][nt*2+1], a_h[mf], b_l[2], b_l[3]);
                    MMA16816(acc[mf][nt*2],   a_l[mf], b_h[0], b_h[1]);
                    MMA16816(acc[mf][nt*2+1], a_l[mf], b_h[2], b_h[3]);
                }
            }
        }
        __syncthreads();
        if (i + 2 < nstg) issue(i + 2, base);
    }

    // ---- epilogue ----
    float* Cfz = 0; __nv_bfloat16* Chz = 0; __nv_bfloat16* Clz = 0;
    if (WF32)  Cfz = Cf + z * sC;
    if (WBF16) { Chz = Ch + z * sC; Clz = Cl + z * sC; }
    const int r0 = bm + wm * 32 + (lane >> 2);
    const int cb = bn + wn * 64 + 2 * (lane & 3);
#pragma unroll
    for (int mf = 0; mf < 2; mf++) {
#pragma unroll
        for (int nfr = 0; nfr < 8; nfr++) {
            const int col = cb + (nfr >> 1) * 16 + (nfr & 1) * 8;
            float bx = 0.0f, by = 0.0f;
            if (HAS_BIAS) {
                float2 b2 = *(const float2*)(bias + col);
                bx = b2.x; by = b2.y;
            }
#pragma unroll
            for (int hf = 0; hf < 2; hf++) {
                const int row = r0 + mf * 16 + hf * 8;
                float x0 = acc[mf][nfr][hf * 2 + 0] * alpha;
                float x1 = acc[mf][nfr][hf * 2 + 1] * alpha;
                if (HAS_BIAS) { x0 += bx; x1 += by; }
                if (RELU) { x0 = fmaxf(x0, 0.0f); x1 = fmaxf(x1, 0.0f); }
                if (WF32)
                    *(float2*)(Cfz + (size_t)row * ldc + col) = make_float2(x0, x1);
                if (WBF16) {
                    __nv_bfloat16 h0 = __float2bfloat16(x0);
                    __nv_bfloat16 h1 = __float2bfloat16(x1);
                    *(__nv_bfloat162*)(Chz + (size_t)row * ldc + col) =
                        __halves2bfloat162(h0, h1);
                    *(__nv_bfloat162*)(Clz + (size_t)row * ldc + col) =
                        __halves2bfloat162(__float2bfloat16(x0 - __bfloat162float(h0)),
                                           __float2bfloat16(x1 - __bfloat162float(h1)));
                }
            }
        }
    }
}

// ---------------- embed + posenc (writes f32 + bf16 hi/lo) ----------------
__global__ __launch_bounds__(256)
void embed_k(const int* __restrict__ idx, const float* __restrict__ emb,
             float* __restrict__ x, __nv_bfloat16* __restrict__ xh,
             __nv_bfloat16* __restrict__ xl)
{
    long tok = blockIdx.x;
    int id = idx[tok];
    if (id >= VOCAB) id = 1;
    int n = (int)(tok & (SEQ - 1));
    int t = threadIdx.x;
    int c0 = t * 4;
    float4 e = ((const float4*)(emb + (size_t)id * DMODEL))[t];

    float nf = (float)n;
    float p0 = (float)c0       * (1.0f / (float)DMODEL);
    float p1 = (float)(c0 + 2) * (1.0f / (float)DMODEL);
    float a0 = nf / powf(10000.0f, p0);
    float a1 = nf / powf(10000.0f, p1);
    float s0, co0, s1, co1;
    sincosf(a0, &s0, &co0);
    sincosf(a1, &s1, &co1);

    float4 r;
    r.x = e.x + s0;  r.y = e.y + co0;
    r.z = e.z + s1;  r.w = e.w + co1;
    ((float4*)(x + (size_t)tok * DMODEL))[t] = r;

    __nv_bfloat16 hx = __float2bfloat16(r.x), hy = __float2bfloat16(r.y);
    __nv_bfloat16 hz = __float2bfloat16(r.z), hw = __float2bfloat16(r.w);
    __nv_bfloat162* ph = (__nv_bfloat162*)(xh + (size_t)tok * DMODEL);
    __nv_bfloat162* pl = (__nv_bfloat162*)(xl + (size_t)tok * DMODEL);
    ph[t * 2]     = __halves2bfloat162(hx, hy);
    ph[t * 2 + 1] = __halves2bfloat162(hz, hw);
    pl[t * 2]     = __halves2bfloat162(__float2bfloat16(r.x - __bfloat162float(hx)),
                                       __float2bfloat16(r.y - __bfloat162float(hy)));
    pl[t * 2 + 1] = __halves2bfloat162(__float2bfloat16(r.z - __bfloat162float(hz)),
                                       __float2bfloat16(r.w - __bfloat162float(hw)));
}

// ---------------- transpose + split: f32 [R,C] -> bf16 hi/lo [C,R] ----------------
__global__ __launch_bounds__(256)
void tconv_k(const float* __restrict__ src, __nv_bfloat16* __restrict__ hi,
             __nv_bfloat16* __restrict__ lo, int R, int C)
{
    __shared__ float s[32][33];
    size_t zoff = (size_t)blockIdx.z * R * C;
    src += zoff; hi += zoff; lo += zoff;
    int bx = blockIdx.x * 32;
    int by = blockIdx.y * 32;
    int tx = threadIdx.x & 31, ty = threadIdx.x >> 5;
#pragma unroll
    for (int k = 0; k < 4; k++)
        s[ty + k * 8][tx] = src[(size_t)(by + ty + k * 8) * C + bx + tx];
    __syncthreads();
#pragma unroll
    for (int k = 0; k < 4; k++) {
        float v = s[tx][ty + k * 8];
        __nv_bfloat16 h = __float2bfloat16(v);
        size_t o = (size_t)(bx + ty + k * 8) * R + by + tx;
        hi[o] = h;
        lo[o] = __float2bfloat16(v - __bfloat162float(h));
    }
}

// ---------------- residual add + layernorm (f32 + bf16 hi/lo out) ----------------
__global__ __launch_bounds__(256)
void add_ln_k(const float* __restrict__ a, const float* __restrict__ b,
              const float* __restrict__ g, const float* __restrict__ be,
              float* __restrict__ o, __nv_bfloat16* __restrict__ oh,
              __nv_bfloat16* __restrict__ ol)
{
    long row = blockIdx.x;
    int t = threadIdx.x;
    float4 x4 = ((const float4*)(a + (size_t)row * DMODEL))[t];
    float4 y4 = ((const float4*)(b + (size_t)row * DMODEL))[t];
    float4 s4;
    s4.x = x4.x + y4.x; s4.y = x4.y + y4.y;
    s4.z = x4.z + y4.z; s4.w = x4.w + y4.w;

    float s = s4.x + s4.y + s4.z + s4.w;
    float q = s4.x * s4.x + s4.y * s4.y + s4.z * s4.z + s4.w * s4.w;
#pragma unroll
    for (int off = 16; off; off >>= 1) {
        s += __shfl_xor_sync(0xffffffffu, s, off);
        q += __shfl_xor_sync(0xffffffffu, q, off);
    }
    __shared__ float ws[8], wq[8];
    if ((t & 31) == 0) { ws[t >> 5] = s; wq[t >> 5] = q; }
    __syncthreads();
    if (t < 32) {
        s = (t < 8) ? ws[t] : 0.0f;
        q = (t < 8) ? wq[t] : 0.0f;
#pragma unroll
        for (int off = 4; off; off >>= 1) {
            s += __shfl_xor_sync(0xffffffffu, s, off);
            q += __shfl_xor_sync(0xffffffffu, q, off);
        }
        if (t == 0) { ws[0] = s; wq[0] = q; }
    }
    __syncthreads();
    float mean = ws[0] * (1.0f / (float)DMODEL);
    float var  = wq[0] * (1.0f / (float)DMODEL) - mean * mean;
    float rstd = rsqrtf(var + 1e-5f);

    float4 g4 = ((const float4*)g)[t];
    float4 b4 = ((const float4*)be)[t];
    float4 r;
    r.x = (s4.x - mean) * rstd * g4.x + b4.x;
    r.y = (s4.y - mean) * rstd * g4.y + b4.y;
    r.z = (s4.z - mean) * rstd * g4.z + b4.z;
    r.w = (s4.w - mean) * rstd * g4.w + b4.w;
    ((float4*)(o + (size_t)row * DMODEL))[t] = r;

    __nv_bfloat16 hx = __float2bfloat16(r.x), hy = __float2bfloat16(r.y);
    __nv_bfloat16 hz = __float2bfloat16(r.z), hw = __float2bfloat16(r.w);
    __nv_bfloat162* ph = (__nv_bfloat162*)(oh + (size_t)row * DMODEL);
    __nv_bfloat162* pl = (__nv_bfloat162*)(ol + (size_t)row * DMODEL);
    ph[t * 2]     = __halves2bfloat162(hx, hy);
    ph[t * 2 + 1] = __halves2bfloat162(hz, hw);
    pl[t * 2]     = __halves2bfloat162(__float2bfloat16(r.x - __bfloat162float(hx)),
                                       __float2bfloat16(r.y - __bfloat162float(hy)));
    pl[t * 2 + 1] = __halves2bfloat162(__float2bfloat16(r.z - __bfloat162float(hz)),
                                       __float2bfloat16(r.w - __bfloat162float(hw)));
}

// ---------------- head: t3@W4 + b4 -> LN(75) -> sigmoid ----------------
__global__ __launch_bounds__(128)
void head_k(const float* __restrict__ t3, const float* __restrict__ W4,
            const float* __restrict__ b4, const float* __restrict__ g3,
            const float* __restrict__ be3, float* __restrict__ out)
{
    long row = blockIdx.x;
    int t = threadIdx.x;
    __shared__ float r[D3];
    ((float4*)r)[t] = ((const float4*)(t3 + (size_t)row * D3))[t];
    __syncthreads();

    __shared__ float vals[NCAT];
    if (t < NCAT) {
        float acc = b4[t];
#pragma unroll 8
        for (int k = 0; k < D3; k++)
            acc = fmaf(r[k], W4[k * NCAT + t], acc);
        vals[t] = acc;
    }
    __syncthreads();

    __shared__ float stat[2];
    if (t == 0) {
        float s = 0.0f;
        for (int i = 0; i < NCAT; i++) s += vals[i];
        float mean = s * (1.0f / (float)NCAT);
        float q = 0.0f;
        for (int i = 0; i < NCAT; i++) { float d = vals[i] - mean; q += d * d; }
        stat[0] = mean;
        stat[1] = rsqrtf(q * (1.0f / (float)NCAT) + 1e-5f);
    }
    __syncthreads();
    if (t < NCAT) {
        float v = (vals[t] - stat[0]) * stat[1] * g3[t] + be3[t];
        out[(size_t)row * NCAT + t] = 1.0f / (1.0f + expf(-v));
    }
}

// ---------------- launch ----------------
extern "C" void kernel_launch(void* const* d_in, const int* in_sizes, int n_in,
                              void* d_out, int out_size)
{
    const int*   idx = (const int*)  d_in[0];
    const float* emb = (const float*)d_in[1];
    const float* Wq  = (const float*)d_in[2];
    const float* bq  = (const float*)d_in[3];
    const float* Wk  = (const float*)d_in[4];
    const float* bk  = (const float*)d_in[5];
    const float* Wv  = (const float*)d_in[6];
    const float* bv  = (const float*)d_in[7];
    const float* Wu  = (const float*)d_in[8];
    const float* bu  = (const float*)d_in[9];
    const float* g1  = (const float*)d_in[10];
    const float* be1 = (const float*)d_in[11];
    const float* W1  = (const float*)d_in[12];
    const float* b1  = (const float*)d_in[13];
    const float* W2  = (const float*)d_in[14];
    const float* b2  = (const float*)d_in[15];
    const float* g2  = (const float*)d_in[16];
    const float* be2 = (const float*)d_in[17];
    const float* W3  = (const float*)d_in[18];
    const float* b3  = (const float*)d_in[19];
    const float* W4  = (const float*)d_in[20];
    const float* b4  = (const float*)d_in[21];
    const float* g3  = (const float*)d_in[22];
    const float* be3 = (const float*)d_in[23];
    float* out = (float*)d_out;

    unsigned char* ar = nullptr;
    cudaGetSymbolAddress((void**)&ar, g_arena);

    float* X_F   = (float*)(ar + OFF_X_F);
    float* K_F   = (float*)(ar + OFF_K_F);
    float* V_F   = (float*)(ar + OFF_V_F);
    float* U_F   = (float*)(ar + OFF_U_F);
    float* H1_F  = (float*)(ar + OFF_H1_F);
    float* FFO_F = (float*)(ar + OFF_FFO_F);
    float* H2_F  = (float*)(ar + OFF_H2_F);
    float* T3_F  = (float*)(ar + OFF_T3_F);
    __nv_bfloat16* XH  = (__nv_bfloat16*)(ar + OFF_XH);
    __nv_bfloat16* XL  = (__nv_bfloat16*)(ar + OFF_XL);
    __nv_bfloat16* QH  = (__nv_bfloat16*)(ar + OFF_QH);
    __nv_bfloat16* QL  = (__nv_bfloat16*)(ar + OFF_QL);
    __nv_bfloat16* KTH = (__nv_bfloat16*)(ar + OFF_KTH);
    __nv_bfloat16* KTL = (__nv_bfloat16*)(ar + OFF_KTL);
    __nv_bfloat16* VTH = (__nv_bfloat16*)(ar + OFF_VTH);
    __nv_bfloat16* VTL = (__nv_bfloat16*)(ar + OFF_VTL);
    __nv_bfloat16* KVH = (__nv_bfloat16*)(ar + OFF_KVH);
    __nv_bfloat16* KVL = (__nv_bfloat16*)(ar + OFF_KVL);
    __nv_bfloat16* AH  = (__nv_bfloat16*)(ar + OFF_AH);
    __nv_bfloat16* AL  = (__nv_bfloat16*)(ar + OFF_AL);
    __nv_bfloat16* H1H = (__nv_bfloat16*)(ar + OFF_H1H);
    __nv_bfloat16* H1L = (__nv_bfloat16*)(ar + OFF_H1L);
    __nv_bfloat16* FBH = (__nv_bfloat16*)(ar + OFF_FBH);
    __nv_bfloat16* FBL = (__nv_bfloat16*)(ar + OFF_FBL);
    __nv_bfloat16* H2H = (__nv_bfloat16*)(ar + OFF_H2H);
    __nv_bfloat16* H2L = (__nv_bfloat16*)(ar + OFF_H2L);
    __nv_bfloat16* WQTH = (__nv_bfloat16*)(ar + OFF_WQTH);
    __nv_bfloat16* WQTL = (__nv_bfloat16*)(ar + OFF_WQTL);
    __nv_bfloat16* WKTH = (__nv_bfloat16*)(ar + OFF_WKTH);
    __nv_bfloat16* WKTL = (__nv_bfloat16*)(ar + OFF_WKTL);
    __nv_bfloat16* WVTH = (__nv_bfloat16*)(ar + OFF_WVTH);
    __nv_bfloat16* WVTL = (__nv_bfloat16*)(ar + OFF_WVTL);
    __nv_bfloat16* WUTH = (__nv_bfloat16*)(ar + OFF_WUTH);
    __nv_bfloat16* WUTL = (__nv_bfloat16*)(ar + OFF_WUTL);
    __nv_bfloat16* W1TH = (__nv_bfloat16*)(ar + OFF_W1TH);
    __nv_bfloat16* W1TL = (__nv_bfloat16*)(ar + OFF_W1TL);
    __nv_bfloat16* W2TH = (__nv_bfloat16*)(ar + OFF_W2TH);
    __nv_bfloat16* W2TL = (__nv_bfloat16*)(ar + OFF_W2TL);
    __nv_bfloat16* W3TH = (__nv_bfloat16*)(ar + OFF_W3TH);
    __nv_bfloat16* W3TL = (__nv_bfloat16*)(ar + OFF_W3TL);

    cudaFuncSetAttribute((const void*)gemm_mma<0,1,0,1>, cudaFuncAttributeMaxDynamicSharedMemorySize, GSMEM_BYTES);
    cudaFuncSetAttribute((const void*)gemm_mma<0,1,1,0>, cudaFuncAttributeMaxDynamicSharedMemorySize, GSMEM_BYTES);
    cudaFuncSetAttribute((const void*)gemm_mma<0,0,0,1>, cudaFuncAttributeMaxDynamicSharedMemorySize, GSMEM_BYTES);
    cudaFuncSetAttribute((const void*)gemm_mma<1,1,0,1>, cudaFuncAttributeMaxDynamicSharedMemorySize, GSMEM_BYTES);
    cudaFuncSetAttribute((const void*)gemm_mma<1,1,1,0>, cudaFuncAttributeMaxDynamicSharedMemorySize, GSMEM_BYTES);

    // 1. embedding + posenc
    embed_k<<<TOK, 256>>>(idx, emb, X_F, XH, XL);

    // 2. weight transpose+split
    tconv_k<<<dim3(32, 32, 1), 256>>>(Wq, WQTH, WQTL, DMODEL, DMODEL);
    tconv_k<<<dim3(32, 32, 1), 256>>>(Wk, WKTH, WKTL, DMODEL, DMODEL);
    tconv_k<<<dim3(32, 32, 1), 256>>>(Wv, WVTH, WVTL, DMODEL, DMODEL);
    tconv_k<<<dim3(32, 32, 1), 256>>>(Wu, WUTH, WUTL, DMODEL, DMODEL);
    tconv_k<<<dim3(128, 32, 1), 256>>>(W1, W1TH, W1TL, DMODEL, FFDIM);
    tconv_k<<<dim3(32, 128, 1), 256>>>(W2, W2TH, W2TL, FFDIM, DMODEL);
    tconv_k<<<dim3(16, 32, 1), 256>>>(W3, W3TH, W3TL, DMODEL, D3);

    // 3. projections
    dim3 gp(DMODEL / BN, TOK / BM, 1);
    gemm_mma<0,1,0,1><<<gp, NTHREAD, GSMEM_BYTES>>>(XH, XL, WQTH, WQTL, bq,
        nullptr, QH, QL, DMODEL, DMODEL, 1.0f, 0, 0, 0);
    gemm_mma<0,1,1,0><<<gp, NTHREAD, GSMEM_BYTES>>>(XH, XL, WKTH, WKTL, bk,
        K_F, nullptr, nullptr, DMODEL, DMODEL, 1.0f, 0, 0, 0);
    gemm_mma<0,1,1,0><<<gp, NTHREAD, GSMEM_BYTES>>>(XH, XL, WVTH, WVTL, bv,
        V_F, nullptr, nullptr, DMODEL, DMODEL, 1.0f, 0, 0, 0);

    // 4. transpose K, V per batch
    tconv_k<<<dim3(32, 64, BATCH), 256>>>(K_F, KTH, KTL, SEQ, DMODEL);
    tconv_k<<<dim3(32, 64, BATCH), 256>>>(V_F, VTH, VTL, SEQ, DMODEL);

    // 5. KVt = (V^T K) / 8  (== (K^T V)^T with scale)
    dim3 gkv(DMODEL / BN, DMODEL / BM, BATCH);
    gemm_mma<0,0,0,1><<<gkv, NTHREAD, GSMEM_BYTES>>>(VTH, VTL, KTH, KTL, nullptr,
        nullptr, KVH, KVL, SEQ, DMODEL, 0.125f,
        (long long)DMODEL * SEQ, (long long)DMODEL * SEQ, (long long)DMODEL * DMODEL);

    // 6. attn = Q @ KV  (B = KVt rows)
    dim3 gat(DMODEL / BN, SEQ / BM, BATCH);
    gemm_mma<0,0,0,1><<<gat, NTHREAD, GSMEM_BYTES>>>(QH, QL, KVH, KVL, nullptr,
        nullptr, AH, AL, DMODEL, DMODEL, 1.0f,
        (long long)SEQ * DMODEL, (long long)DMODEL * DMODEL, (long long)SEQ * DMODEL);

    // 7. u = attn @ Wu + bu
    gemm_mma<0,1,1,0><<<gp, NTHREAD, GSMEM_BYTES>>>(AH, AL, WUTH, WUTL, bu,
        U_F, nullptr, nullptr, DMODEL, DMODEL, 1.0f, 0, 0, 0);

    // 8. h1 = LN(x + u)
    add_ln_k<<<TOK, 256>>>(X_F, U_F, g1, be1, H1_F, H1H, H1L);

    // 9. ff = relu(h1 @ W1 + b1)
    dim3 gf1(FFDIM / BN, TOK / BM, 1);
    gemm_mma<1,1,0,1><<<gf1, NTHREAD, GSMEM_BYTES>>>(H1H, H1L, W1TH, W1TL, b1,
        nullptr, FBH, FBL, DMODEL, FFDIM, 1.0f, 0, 0, 0);

    // 10. ffo = ff @ W2 + b2
    gemm_mma<0,1,1,0><<<gp, NTHREAD, GSMEM_BYTES>>>(FBH, FBL, W2TH, W2TL, b2,
        FFO_F, nullptr, nullptr, FFDIM, DMODEL, 1.0f, 0, 0, 0);

    // 11. h2 = LN(h1 + ffo)
    add_ln_k<<<TOK, 256>>>(H1_F, FFO_F, g2, be2, H2_F, H2H, H2L);

    // 12. t3 = relu(h2 @ W3 + b3)
    dim3 g3g(D3 / BN, TOK / BM, 1);
    gemm_mma<1,1,1,0><<<g3g, NTHREAD, GSMEM_BYTES>>>(H2H, H2L, W3TH, W3TL, b3,
        T3_F, nullptr, nullptr, DMODEL, D3, 1.0f, 0, 0, 0);

    // 13. out
    head_k<<<TOK, 128>>>(T3_F, W4, b4, g3, be3, out);

    (void)in_sizes; (void)n_in; (void)out_size;
}

// round 13
// speedup vs baseline: 1.3539x; 1.3539x over previous
#include <cuda_runtime.h>
#include <cuda_fp16.h>
#include <math.h>
#include <stdint.h>

// ---------------- problem constants ----------------
#define BATCH   8
#define SEQ     2048
#define DMODEL  1024
#define FFDIM   4096
#define NCAT    75
#define D3      512
#define VOCAB   32000
#define TOK     (BATCH*SEQ)    // 16384

// ---------------- arena ----------------
#define MB (1ull<<20)
#define OFF_X_F    (0ull*MB)     // [16384,1024] f32
#define OFF_K_F    (64ull*MB)
#define OFF_V_F    (128ull*MB)
#define OFF_U_F    (192ull*MB)
#define OFF_H1_F   (256ull*MB)
#define OFF_FFO_F  (320ull*MB)
#define OFF_H2_F   (384ull*MB)
#define OFF_T3_F   (448ull*MB)   // [16384,512] f32
#define OFF_XH     (480ull*MB)   // fp16 [16384,1024]
#define OFF_XL     (512ull*MB)
#define OFF_QH     (544ull*MB)
#define OFF_QL     (576ull*MB)
#define OFF_KTH    (608ull*MB)   // fp16 [8][1024,2048]
#define OFF_VTH    (672ull*MB)
#define OFF_VTL    (704ull*MB)
#define OFF_KVH    (736ull*MB)   // fp16 [8][1024,1024]
#define OFF_AH     (768ull*MB)
#define OFF_AL     (800ull*MB)
#define OFF_H1H    (832ull*MB)
#define OFF_H1L    (864ull*MB)
#define OFF_FBH    (896ull*MB)   // fp16 [16384,4096]
#define OFF_FBL    (1024ull*MB)
#define OFF_H2H    (1152ull*MB)
#define OFF_H2L    (1184ull*MB)
#define OFF_WQTH   (1216ull*MB)
#define OFF_WKTH   (1220ull*MB)
#define OFF_WVTH   (1224ull*MB)
#define OFF_WUTH   (1228ull*MB)
#define OFF_W1TH   (1232ull*MB)  // [4096,1024] fp16
#define OFF_W2TH   (1248ull*MB)  // [1024,4096] fp16
#define OFF_W3TH   (1264ull*MB)  // [512,1024] fp16
#define ARENA_BYTES (1266ull*MB)

__device__ __align__(1024) unsigned char g_arena[ARENA_BYTES];

// ---------------- PTX helpers ----------------
__device__ __forceinline__ uint32_t smem_u32(const void* p) {
    uint32_t a;
    asm("{ .reg .u64 t; cvta.to.shared.u64 t, %1; cvt.u32.u64 %0, t; }" : "=r"(a) : "l"(p));
    return a;
}
__device__ __forceinline__ void cp16(uint32_t s, const void* g) {
    asm volatile("cp.async.cg.shared.global [%0], [%1], 16;" :: "r"(s), "l"(g));
}
#define CP_COMMIT() asm volatile("cp.async.commit_group;" ::: "memory")
#define CP_WAIT2()  asm volatile("cp.async.wait_group 2;"  ::: "memory")

#define LDSM_X4(R, addr) \
    asm volatile("ldmatrix.sync.aligned.m8n8.x4.shared.b16 {%0,%1,%2,%3}, [%4];" \
        : "=r"((R)[0]), "=r"((R)[1]), "=r"((R)[2]), "=r"((R)[3]) : "r"(addr))

#define MMA16816(ac, A, B0, B1) \
    asm volatile("mma.sync.aligned.m16n8k16.row.col.f32.f16.f16.f32 " \
        "{%0,%1,%2,%3},{%4,%5,%6,%7},{%8,%9},{%0,%1,%2,%3};" \
        : "+f"((ac)[0]), "+f"((ac)[1]), "+f"((ac)[2]), "+f"((ac)[3]) \
        : "r"((A)[0]), "r"((A)[1]), "r"((A)[2]), "r"((A)[3]), "r"(B0), "r"(B1))

// ---------------- fp16 split helpers ----------------
__device__ __forceinline__ __half2 pack_h2(float a, float b) {
    return __halves2half2(__float2half_rn(a), __float2half_rn(b));
}
__device__ __forceinline__ __half2 pack_lo_h2(float a, float b, __half2 hi) {
    return __halves2half2(__float2half_rn(a - __half2float(__low2half(hi))),
                          __float2half_rn(b - __half2float(__high2half(hi))));
}

// ---------------- fp16 split mma.sync GEMM ----------------
// C[M,N] = alpha * ((Ah+Al) @ Bh^T) (+bias) (opt relu)
// A: [M,K] fp16 hi/lo K-major rows; B: [N,K] fp16 hi K-major rows.
// Tile: BM=128, BN=128, BK=64. 8 warps = 4(m) x 2(n), warp tile 32x64.
// 3-stage cp.async pipeline (3 x 48KB). SW128 swizzle: off ^ ((off>>3)&0x70).
#define BM 128
#define BN 128
#define BK 64
#define STAGE_BYTES 49152      // Ah 16K | Al 16K | Bh 16K
#define NSTAGE 3
#define GSMEM_BYTES (NSTAGE*STAGE_BYTES)

template<int RELU, int HAS_BIAS, int WF32, int WHI, int WLO>
__global__ __launch_bounds__(256)
void gemm_mma(const __half* __restrict__ Ah, const __half* __restrict__ Al,
              const __half* __restrict__ Bh,
              const float* __restrict__ bias,
              float* __restrict__ Cf, __half* __restrict__ Ch,
              __half* __restrict__ Cl,
              int Kd, int ldc, float alpha,
              long long sA, long long sB, long long sC)
{
    extern __shared__ char smc[];
    const int tid  = threadIdx.x;
    const int wid  = tid >> 5;
    const int lane = tid & 31;
    const int bm   = blockIdx.y * BM;
    const int bn   = blockIdx.x * BN;
    const size_t z = blockIdx.z;

    const char* gAh = (const char*)(Ah + z * sA + (size_t)bm * Kd);
    const char* gAl = (const char*)(Al + z * sA + (size_t)bm * Kd);
    const char* gBh = (const char*)(Bh + z * sB + (size_t)bn * Kd);

    const uint32_t sb = smem_u32(smc);
    const size_t Kb = (size_t)Kd * 2;      // row stride in bytes

    const int ck = tid & 7;  // k-chunk (16B) within row

    auto issue = [&](int s, uint32_t sbase) {
        const size_t kof = (size_t)s * (BK * 2) + (size_t)ck * 16;
#pragma unroll
        for (int j = 0; j < 4; j++) {
            const int row = (tid + j * 256) >> 3;
            const size_t go = (size_t)row * Kb + kof;
            const uint32_t so = row * 128 + ((ck * 16) ^ ((row & 7) * 16));
            cp16(sbase + so,         gAh + go);
            cp16(sbase + 16384 + so, gAl + go);
            cp16(sbase + 32768 + so, gBh + go);
        }
        CP_COMMIT();
    };

    const int nstg = Kd / BK;
    issue(0, sb);
    issue(1, sb + STAGE_BYTES);
    issue(2, sb + 2 * STAGE_BYTES);

    const int wm = wid & 3, wn = wid >> 2;
    const int mArow = wm * 32 + (lane & 15);
    const int aKh   = lane >> 4;                       // k-half for A ldmatrix
    const int bNrow = wn * 64 + (lane & 7) + ((lane >> 4) << 3);
    const int bKh   = (lane >> 3) & 1;                 // k-half for B ldmatrix

    float acc[2][8][4];
#pragma unroll
    for (int i = 0; i < 2; i++)
#pragma unroll
        for (int j = 0; j < 8; j++)
#pragma unroll
            for (int q = 0; q < 4; q++) acc[i][j][q] = 0.0f;

#pragma unroll 1
    for (int i = 0; i < nstg; i++) {
        CP_WAIT2();
        __syncthreads();
        const uint32_t base = sb + (uint32_t)(i % 3) * STAGE_BYTES;

#pragma unroll
        for (int ks = 0; ks < 4; ks++) {
            const uint32_t kb_a = ks * 32 + aKh * 16;
            const uint32_t kb_b = ks * 32 + bKh * 16;
            uint32_t a_h[2][4], a_l[2][4];
#pragma unroll
            for (int mf = 0; mf < 2; mf++) {
                const int m = mArow + mf * 16;
                const uint32_t so = m * 128 + (kb_a ^ ((m & 7) * 16));
                LDSM_X4(a_h[mf], base + so);
                LDSM_X4(a_l[mf], base + 16384 + so);
            }
#pragma unroll
            for (int nt = 0; nt < 4; nt++) {
                const int n = bNrow + nt * 16;
                const uint32_t so = n * 128 + (kb_b ^ ((n & 7) * 16));
                uint32_t b_h[4];
                LDSM_X4(b_h, base + 32768 + so);
#pragma unroll
                for (int mf = 0; mf < 2; mf++) {
                    MMA16816(acc[mf][nt*2],   a_h[mf], b_h[0], b_h[1]);
                    MMA16816(acc[mf][nt*2+1], a_h[mf], b_h[2], b_h[3]);
                    MMA16816(acc[mf][nt*2],   a_l[mf], b_h[0], b_h[1]);
                    MMA16816(acc[mf][nt*2+1], a_l[mf], b_h[2], b_h[3]);
                }
            }
        }
        __syncthreads();
        if (i + 3 < nstg) issue(i + 3, base);
    }

    // ---- epilogue ----
    float* Cfz = 0; __half* Chz = 0; __half* Clz = 0;
    if (WF32) Cfz = Cf + z * sC;
    if (WHI)  Chz = Ch + z * sC;
    if (WLO)  Clz = Cl + z * sC;
    const int r0 = bm + wm * 32 + (lane >> 2);
    const int cb = bn + wn * 64 + 2 * (lane & 3);
#pragma unroll
    for (int mf = 0; mf < 2; mf++) {
#pragma unroll
        for (int nfr = 0; nfr < 8; nfr++) {
            const int col = cb + (nfr >> 1) * 16 + (nfr & 1) * 8;
            float bx = 0.0f, by = 0.0f;
            if (HAS_BIAS) {
                float2 b2 = *(const float2*)(bias + col);
                bx = b2.x; by = b2.y;
            }
#pragma unroll
            for (int hf = 0; hf < 2; hf++) {
                const int row = r0 + mf * 16 + hf * 8;
                float x0 = acc[mf][nfr][hf * 2 + 0] * alpha;
                float x1 = acc[mf][nfr][hf * 2 + 1] * alpha;
                if (HAS_BIAS) { x0 += bx; x1 += by; }
                if (RELU) { x0 = fmaxf(x0, 0.0f); x1 = fmaxf(x1, 0.0f); }
                if (WF32)
                    *(float2*)(Cfz + (size_t)row * ldc + col) = make_float2(x0, x1);
                if (WHI) {
                    __half2 h2v = pack_h2(x0, x1);
                    *(__half2*)(Chz + (size_t)row * ldc + col) = h2v;
                    if (WLO)
                        *(__half2*)(Clz + (size_t)row * ldc + col) = pack_lo_h2(x0, x1, h2v);
                }
            }
        }
    }
}

// ---------------- embed + posenc (writes f32 + fp16 hi/lo) ----------------
__global__ __launch_bounds__(256)
void embed_k(const int* __restrict__ idx, const float* __restrict__ emb,
             float* __restrict__ x, __half* __restrict__ xh,
             __half* __restrict__ xl)
{
    long tok = blockIdx.x;
    int id = idx[tok];
    if (id >= VOCAB) id = 1;
    int n = (int)(tok & (SEQ - 1));
    int t = threadIdx.x;
    int c0 = t * 4;
    float4 e = ((const float4*)(emb + (size_t)id * DMODEL))[t];

    float nf = (float)n;
    float p0 = (float)c0       * (1.0f / (float)DMODEL);
    float p1 = (float)(c0 + 2) * (1.0f / (float)DMODEL);
    float a0 = nf / powf(10000.0f, p0);
    float a1 = nf / powf(10000.0f, p1);
    float s0, co0, s1, co1;
    sincosf(a0, &s0, &co0);
    sincosf(a1, &s1, &co1);

    float4 r;
    r.x = e.x + s0;  r.y = e.y + co0;
    r.z = e.z + s1;  r.w = e.w + co1;
    ((float4*)(x + (size_t)tok * DMODEL))[t] = r;

    __half2* ph = (__half2*)(xh + (size_t)tok * DMODEL);
    __half2* pl = (__half2*)(xl + (size_t)tok * DMODEL);
    __half2 h0 = pack_h2(r.x, r.y);
    __half2 h1 = pack_h2(r.z, r.w);
    ph[t * 2]     = h0;
    ph[t * 2 + 1] = h1;
    pl[t * 2]     = pack_lo_h2(r.x, r.y, h0);
    pl[t * 2 + 1] = pack_lo_h2(r.z, r.w, h1);
}

// ---------------- transpose + split: f32 [R,C] -> fp16 hi(/lo) [C,R] ----------------
template<int WLO>
__global__ __launch_bounds__(256)
void tconv_k(const float* __restrict__ src, __half* __restrict__ hi,
             __half* __restrict__ lo, int R, int C)
{
    __shared__ float s[32][33];
    size_t zoff = (size_t)blockIdx.z * R * C;
    src += zoff; hi += zoff;
    if (WLO) lo += zoff;
    int bx = blockIdx.x * 32;
    int by = blockIdx.y * 32;
    int tx = threadIdx.x & 31, ty = threadIdx.x >> 5;
#pragma unroll
    for (int k = 0; k < 4; k++)
        s[ty + k * 8][tx] = src[(size_t)(by + ty + k * 8) * C + bx + tx];
    __syncthreads();
#pragma unroll
    for (int k = 0; k < 4; k++) {
        float v = s[tx][ty + k * 8];
        __half h = __float2half_rn(v);
        size_t o = (size_t)(bx + ty + k * 8) * R + by + tx;
        hi[o] = h;
        if (WLO) lo[o] = __float2half_rn(v - __half2float(h));
    }
}

// ---------------- residual add + layernorm (f32 + fp16 hi/lo out) ----------------
__global__ __launch_bounds__(256)
void add_ln_k(const float* __restrict__ a, const float* __restrict__ b,
              const float* __restrict__ g, const float* __restrict__ be,
              float* __restrict__ o, __half* __restrict__ oh,
              __half* __restrict__ ol)
{
    long row = blockIdx.x;
    int t = threadIdx.x;
    float4 x4 = ((const float4*)(a + (size_t)row * DMODEL))[t];
    float4 y4 = ((const float4*)(b + (size_t)row * DMODEL))[t];
    float4 s4;
    s4.x = x4.x + y4.x; s4.y = x4.y + y4.y;
    s4.z = x4.z + y4.z; s4.w = x4.w + y4.w;

    float s = s4.x + s4.y + s4.z + s4.w;
    float q = s4.x * s4.x + s4.y * s4.y + s4.z * s4.z + s4.w * s4.w;
#pragma unroll
    for (int off = 16; off; off >>= 1) {
        s += __shfl_xor_sync(0xffffffffu, s, off);
        q += __shfl_xor_sync(0xffffffffu, q, off);
    }
    __shared__ float ws[8], wq[8];
    if ((t & 31) == 0) { ws[t >> 5] = s; wq[t >> 5] = q; }
    __syncthreads();
    if (t < 32) {
        s = (t < 8) ? ws[t] : 0.0f;
        q = (t < 8) ? wq[t] : 0.0f;
#pragma unroll
        for (int off = 4; off; off >>= 1) {
            s += __shfl_xor_sync(0xffffffffu, s, off);
            q += __shfl_xor_sync(0xffffffffu, q, off);
        }
        if (t == 0) { ws[0] = s; wq[0] = q; }
    }
    __syncthreads();
    float mean = ws[0] * (1.0f / (float)DMODEL);
    float var  = wq[0] * (1.0f / (float)DMODEL) - mean * mean;
    float rstd = rsqrtf(var + 1e-5f);

    float4 g4 = ((const float4*)g)[t];
    float4 b4 = ((const float4*)be)[t];
    float4 r;
    r.x = (s4.x - mean) * rstd * g4.x + b4.x;
    r.y = (s4.y - mean) * rstd * g4.y + b4.y;
    r.z = (s4.z - mean) * rstd * g4.z + b4.z;
    r.w = (s4.w - mean) * rstd * g4.w + b4.w;
    ((float4*)(o + (size_t)row * DMODEL))[t] = r;

    __half2* ph = (__half2*)(oh + (size_t)row * DMODEL);
    __half2* pl = (__half2*)(ol + (size_t)row * DMODEL);
    __half2 h0 = pack_h2(r.x, r.y);
    __half2 h1 = pack_h2(r.z, r.w);
    ph[t * 2]     = h0;
    ph[t * 2 + 1] = h1;
    pl[t * 2]     = pack_lo_h2(r.x, r.y, h0);
    pl[t * 2 + 1] = pack_lo_h2(r.z, r.w, h1);
}

// ---------------- head: t3@W4 + b4 -> LN(75) -> sigmoid ----------------
__global__ __launch_bounds__(128)
void head_k(const float* __restrict__ t3, const float* __restrict__ W4,
            const float* __restrict__ b4, const float* __restrict__ g3,
            const float* __restrict__ be3, float* __restrict__ out)
{
    long row = blockIdx.x;
    int t = threadIdx.x;
    __shared__ float r[D3];
    ((float4*)r)[t] = ((const float4*)(t3 + (size_t)row * D3))[t];
    __syncthreads();

    __shared__ float vals[NCAT];
    if (t < NCAT) {
        float acc = b4[t];
#pragma unroll 8
        for (int k = 0; k < D3; k++)
            acc = fmaf(r[k], W4[k * NCAT + t], acc);
        vals[t] = acc;
    }
    __syncthreads();

    __shared__ float stat[2];
    if (t == 0) {
        float s = 0.0f;
        for (int i = 0; i < NCAT; i++) s += vals[i];
        float mean = s * (1.0f / (float)NCAT);
        float q = 0.0f;
        for (int i = 0; i < NCAT; i++) { float d = vals[i] - mean; q += d * d; }
        stat[0] = mean;
        stat[1] = rsqrtf(q * (1.0f / (float)NCAT) + 1e-5f);
    }
    __syncthreads();
    if (t < NCAT) {
        float v = (vals[t] - stat[0]) * stat[1] * g3[t] + be3[t];
        out[(size_t)row * NCAT + t] = 1.0f / (1.0f + expf(-v));
    }
}

// ---------------- launch ----------------
extern "C" void kernel_launch(void* const* d_in, const int* in_sizes, int n_in,
                              void* d_out, int out_size)
{
    const int*   idx = (const int*)  d_in[0];
    const float* emb = (const float*)d_in[1];
    const float* Wq  = (const float*)d_in[2];
    const float* bq  = (const float*)d_in[3];
    const float* Wk  = (const float*)d_in[4];
    const float* bk  = (const float*)d_in[5];
    const float* Wv  = (const float*)d_in[6];
    const float* bv  = (const float*)d_in[7];
    const float* Wu  = (const float*)d_in[8];
    const float* bu  = (const float*)d_in[9];
    const float* g1  = (const float*)d_in[10];
    const float* be1 = (const float*)d_in[11];
    const float* W1  = (const float*)d_in[12];
    const float* b1  = (const float*)d_in[13];
    const float* W2  = (const float*)d_in[14];
    const float* b2  = (const float*)d_in[15];
    const float* g2  = (const float*)d_in[16];
    const float* be2 = (const float*)d_in[17];
    const float* W3  = (const float*)d_in[18];
    const float* b3  = (const float*)d_in[19];
    const float* W4  = (const float*)d_in[20];
    const float* b4  = (const float*)d_in[21];
    const float* g3  = (const float*)d_in[22];
    const float* be3 = (const float*)d_in[23];
    float* out = (float*)d_out;

    unsigned char* ar = nullptr;
    cudaGetSymbolAddress((void**)&ar, g_arena);

    float* X_F   = (float*)(ar + OFF_X_F);
    float* K_F   = (float*)(ar + OFF_K_F);
    float* V_F   = (float*)(ar + OFF_V_F);
    float* U_F   = (float*)(ar + OFF_U_F);
    float* H1_F  = (float*)(ar + OFF_H1_F);
    float* FFO_F = (float*)(ar + OFF_FFO_F);
    float* H2_F  = (float*)(ar + OFF_H2_F);
    float* T3_F  = (float*)(ar + OFF_T3_F);
    __half* XH  = (__half*)(ar + OFF_XH);
    __half* XL  = (__half*)(ar + OFF_XL);
    __half* QH  = (__half*)(ar + OFF_QH);
    __half* QL  = (__half*)(ar + OFF_QL);
    __half* KTH = (__half*)(ar + OFF_KTH);
    __half* VTH = (__half*)(ar + OFF_VTH);
    __half* VTL = (__half*)(ar + OFF_VTL);
    __half* KVH = (__half*)(ar + OFF_KVH);
    __half* AH  = (__half*)(ar + OFF_AH);
    __half* AL  = (__half*)(ar + OFF_AL);
    __half* H1H = (__half*)(ar + OFF_H1H);
    __half* H1L = (__half*)(ar + OFF_H1L);
    __half* FBH = (__half*)(ar + OFF_FBH);
    __half* FBL = (__half*)(ar + OFF_FBL);
    __half* H2H = (__half*)(ar + OFF_H2H);
    __half* H2L = (__half*)(ar + OFF_H2L);
    __half* WQTH = (__half*)(ar + OFF_WQTH);
    __half* WKTH = (__half*)(ar + OFF_WKTH);
    __half* WVTH = (__half*)(ar + OFF_WVTH);
    __half* WUTH = (__half*)(ar + OFF_WUTH);
    __half* W1TH = (__half*)(ar + OFF_W1TH);
    __half* W2TH = (__half*)(ar + OFF_W2TH);
    __half* W3TH = (__half*)(ar + OFF_W3TH);

    cudaFuncSetAttribute((const void*)gemm_mma<0,1,0,1,1>, cudaFuncAttributeMaxDynamicSharedMemorySize, GSMEM_BYTES);
    cudaFuncSetAttribute((const void*)gemm_mma<0,1,1,0,0>, cudaFuncAttributeMaxDynamicSharedMemorySize, GSMEM_BYTES);
    cudaFuncSetAttribute((const void*)gemm_mma<0,0,0,1,0>, cudaFuncAttributeMaxDynamicSharedMemorySize, GSMEM_BYTES);
    cudaFuncSetAttribute((const void*)gemm_mma<0,0,0,1,1>, cudaFuncAttributeMaxDynamicSharedMemorySize, GSMEM_BYTES);
    cudaFuncSetAttribute((const void*)gemm_mma<1,1,0,1,1>, cudaFuncAttributeMaxDynamicSharedMemorySize, GSMEM_BYTES);
    cudaFuncSetAttribute((const void*)gemm_mma<1,1,1,0,0>, cudaFuncAttributeMaxDynamicSharedMemorySize, GSMEM_BYTES);

    // 1. embedding + posenc
    embed_k<<<TOK, 256>>>(idx, emb, X_F, XH, XL);

    // 2. weight transpose + fp16 (hi only — weights are the B operand)
    tconv_k<0><<<dim3(32, 32, 1), 256>>>(Wq, WQTH, nullptr, DMODEL, DMODEL);
    tconv_k<0><<<dim3(32, 32, 1), 256>>>(Wk, WKTH, nullptr, DMODEL, DMODEL);
    tconv_k<0><<<dim3(32, 32, 1), 256>>>(Wv, WVTH, nullptr, DMODEL, DMODEL);
    tconv_k<0><<<dim3(32, 32, 1), 256>>>(Wu, WUTH, nullptr, DMODEL, DMODEL);
    tconv_k<0><<<dim3(128, 32, 1), 256>>>(W1, W1TH, nullptr, DMODEL, FFDIM);
    tconv_k<0><<<dim3(32, 128, 1), 256>>>(W2, W2TH, nullptr, FFDIM, DMODEL);
    tconv_k<0><<<dim3(16, 32, 1), 256>>>(W3, W3TH, nullptr, DMODEL, D3);

    // 3. projections: Q = hi/lo (A of attn); K,V = f32 (then transposed)
    dim3 gp(DMODEL / BN, TOK / BM, 1);
    gemm_mma<0,1,0,1,1><<<gp, 256, GSMEM_BYTES>>>(XH, XL, WQTH, bq,
        nullptr, QH, QL, DMODEL, DMODEL, 1.0f, 0, 0, 0);
    gemm_mma<0,1,1,0,0><<<gp, 256, GSMEM_BYTES>>>(XH, XL, WKTH, bk,
        K_F, nullptr, nullptr, DMODEL, DMODEL, 1.0f, 0, 0, 0);
    gemm_mma<0,1,1,0,0><<<gp, 256, GSMEM_BYTES>>>(XH, XL, WVTH, bv,
        V_F, nullptr, nullptr, DMODEL, DMODEL, 1.0f, 0, 0, 0);

    // 4. transpose K (hi only: B of KV gemm), V (hi/lo: A of KV gemm)
    tconv_k<0><<<dim3(32, 64, BATCH), 256>>>(K_F, KTH, nullptr, SEQ, DMODEL);
    tconv_k<1><<<dim3(32, 64, BATCH), 256>>>(V_F, VTH, VTL, SEQ, DMODEL);

    // 5. KVt = (V^T K) / 8 ; hi only (B of attn gemm)
    dim3 gkv(DMODEL / BN, DMODEL / BM, BATCH);
    gemm_mma<0,0,0,1,0><<<gkv, 256, GSMEM_BYTES>>>(VTH, VTL, KTH, nullptr,
        nullptr, KVH, nullptr, SEQ, DMODEL, 0.125f,
        (long long)DMODEL * SEQ, (long long)DMODEL * SEQ, (long long)DMODEL * DMODEL);

    // 6. attn = Q @ KV ; hi/lo (A of u gemm)
    dim3 gat(DMODEL / BN, SEQ / BM, BATCH);
    gemm_mma<0,0,0,1,1><<<gat, 256, GSMEM_BYTES>>>(QH, QL, KVH, nullptr,
        nullptr, AH, AL, DMODEL, DMODEL, 1.0f,
        (long long)SEQ * DMODEL, (long long)DMODEL * DMODEL, (long long)SEQ * DMODEL);

    // 7. u = attn @ Wu + bu  (f32)
    gemm_mma<0,1,1,0,0><<<gp, 256, GSMEM_BYTES>>>(AH, AL, WUTH, bu,
        U_F, nullptr, nullptr, DMODEL, DMODEL, 1.0f, 0, 0, 0);

    // 8. h1 = LN(x + u)
    add_ln_k<<<TOK, 256>>>(X_F, U_F, g1, be1, H1_F, H1H, H1L);

    // 9. ff = relu(h1 @ W1 + b1)  hi/lo (A of ff2)
    dim3 gf1(FFDIM / BN, TOK / BM, 1);
    gemm_mma<1,1,0,1,1><<<gf1, 256, GSMEM_BYTES>>>(H1H, H1L, W1TH, b1,
        nullptr, FBH, FBL, DMODEL, FFDIM, 1.0f, 0, 0, 0);

    // 10. ffo = ff @ W2 + b2  (f32)
    gemm_mma<0,1,1,0,0><<<gp, 256, GSMEM_BYTES>>>(FBH, FBL, W2TH, b2,
        FFO_F, nullptr, nullptr, FFDIM, DMODEL, 1.0f, 0, 0, 0);

    // 11. h2 = LN(h1 + ffo)
    add_ln_k<<<TOK, 256>>>(H1_F, FFO_F, g2, be2, H2_F, H2H, H2L);

    // 12. t3 = relu(h2 @ W3 + b3)  (f32)
    dim3 g3g(D3 / BN, TOK / BM, 1);
    gemm_mma<1,1,1,0,0><<<g3g, 256, GSMEM_BYTES>>>(H2H, H2L, W3TH, b3,
        T3_F, nullptr, nullptr, DMODEL, D3, 1.0f, 0, 0, 0);

    // 13. out
    head_k<<<TOK, 128>>>(T3_F, W4, b4, g3, be3, out);

    (void)in_sizes; (void)n_in; (void)out_size;
}

// round 16
// speedup vs baseline: 2.0617x; 1.5228x over previous
#include <cuda_runtime.h>
#include <cuda_fp16.h>
#include <math.h>
#include <stdint.h>

// ---------------- problem constants ----------------
#define BATCH   8
#define SEQ     2048
#define DMODEL  1024
#define FFDIM   4096
#define NCAT    75
#define D3      512
#define VOCAB   32000
#define TOK     (BATCH*SEQ)    // 16384

// ---------------- arena ----------------
#define MB (1ull<<20)
#define OFF_X_F    (0ull*MB)     // [16384,1024] f32
#define OFF_K_F    (64ull*MB)
#define OFF_V_F    (128ull*MB)
#define OFF_U_F    (192ull*MB)
#define OFF_H1_F   (256ull*MB)
#define OFF_FFO_F  (320ull*MB)
#define OFF_H2_F   (384ull*MB)
#define OFF_T3_F   (448ull*MB)   // [16384,512] f32
#define OFF_XH     (480ull*MB)   // fp16 [16384,1024]
#define OFF_QH     (544ull*MB)
#define OFF_KTH    (608ull*MB)   // fp16 [8][1024,2048]
#define OFF_VTH    (672ull*MB)
#define OFF_KVH    (736ull*MB)   // fp16 [8][1024,1024]
#define OFF_AH     (768ull*MB)
#define OFF_H1H    (832ull*MB)
#define OFF_FBH    (896ull*MB)   // fp16 [16384,4096]
#define OFF_H2H    (1152ull*MB)
#define OFF_WQTH   (1216ull*MB)
#define OFF_WKTH   (1220ull*MB)
#define OFF_WVTH   (1224ull*MB)
#define OFF_WUTH   (1228ull*MB)
#define OFF_W1TH   (1232ull*MB)  // [4096,1024] fp16
#define OFF_W2TH   (1248ull*MB)  // [1024,4096] fp16
#define OFF_W3TH   (1264ull*MB)  // [512,1024] fp16
#define ARENA_BYTES (1266ull*MB)

__device__ __align__(1024) unsigned char g_arena[ARENA_BYTES];

// ---------------- PTX helpers ----------------
__device__ __forceinline__ uint32_t smem_u32(const void* p) {
    uint32_t a;
    asm("{ .reg .u64 t; cvta.to.shared.u64 t, %1; cvt.u32.u64 %0, t; }" : "=r"(a) : "l"(p));
    return a;
}
__device__ __forceinline__ void cp16(uint32_t s, const void* g) {
    asm volatile("cp.async.cg.shared.global [%0], [%1], 16;" :: "r"(s), "l"(g));
}
#define CP_COMMIT() asm volatile("cp.async.commit_group;" ::: "memory")
#define CP_WAIT3()  asm volatile("cp.async.wait_group 3;"  ::: "memory")

#define LDSM_X4(R, addr) \
    asm volatile("ldmatrix.sync.aligned.m8n8.x4.shared.b16 {%0,%1,%2,%3}, [%4];" \
        : "=r"((R)[0]), "=r"((R)[1]), "=r"((R)[2]), "=r"((R)[3]) : "r"(addr))

#define MMA16816(ac, A, B0, B1) \
    asm volatile("mma.sync.aligned.m16n8k16.row.col.f32.f16.f16.f32 " \
        "{%0,%1,%2,%3},{%4,%5,%6,%7},{%8,%9},{%0,%1,%2,%3};" \
        : "+f"((ac)[0]), "+f"((ac)[1]), "+f"((ac)[2]), "+f"((ac)[3]) \
        : "r"((A)[0]), "r"((A)[1]), "r"((A)[2]), "r"((A)[3]), "r"(B0), "r"(B1))

__device__ __forceinline__ __half2 pack_h2(float a, float b) {
    return __halves2half2(__float2half_rn(a), __float2half_rn(b));
}

// ---------------- fp16 mma.sync GEMM ----------------
// C[M,N] = alpha * (Ah @ Bh^T) (+bias) (opt relu)
// A: [M,K] fp16 K-major rows; B: [N,K] fp16 K-major rows.
// Tile: BM=128, BN=128, BK=64. 8 warps = 4(m) x 2(n), warp tile 32x64.
// 4-stage cp.async pipeline (4 x 32KB). SW128 swizzle: off ^ ((off>>3)&0x70).
#define BM 128
#define BN 128
#define BK 64
#define STAGE_BYTES 32768      // Ah 16K | Bh 16K
#define NSTAGE 4
#define GSMEM_BYTES (NSTAGE*STAGE_BYTES)

template<int RELU, int HAS_BIAS, int WF32, int WHI>
__global__ __launch_bounds__(256)
void gemm_mma(const __half* __restrict__ Ah, const __half* __restrict__ Bh,
              const float* __restrict__ bias,
              float* __restrict__ Cf, __half* __restrict__ Ch,
              int Kd, int ldc, float alpha,
              long long sA, long long sB, long long sC)
{
    extern __shared__ char smc[];
    const int tid  = threadIdx.x;
    const int wid  = tid >> 5;
    const int lane = tid & 31;
    const int bm   = blockIdx.y * BM;
    const int bn   = blockIdx.x * BN;
    const size_t z = blockIdx.z;

    const char* gAh = (const char*)(Ah + z * sA + (size_t)bm * Kd);
    const char* gBh = (const char*)(Bh + z * sB + (size_t)bn * Kd);

    const uint32_t sb = smem_u32(smc);
    const size_t Kb = (size_t)Kd * 2;      // row stride in bytes

    const int ck = tid & 7;  // k-chunk (16B) within row

    auto issue = [&](int s, uint32_t sbase) {
        const size_t kof = (size_t)s * (BK * 2) + (size_t)ck * 16;
#pragma unroll
        for (int j = 0; j < 4; j++) {
            const int row = (tid + j * 256) >> 3;
            const size_t go = (size_t)row * Kb + kof;
            const uint32_t so = row * 128 + ((ck * 16) ^ ((row & 7) * 16));
            cp16(sbase + so,         gAh + go);
            cp16(sbase + 16384 + so, gBh + go);
        }
        CP_COMMIT();
    };

    const int nstg = Kd / BK;
    issue(0, sb);
    issue(1, sb + STAGE_BYTES);
    issue(2, sb + 2 * STAGE_BYTES);
    issue(3, sb + 3 * STAGE_BYTES);

    const int wm = wid & 3, wn = wid >> 2;
    const int mArow = wm * 32 + (lane & 15);
    const int aKh   = lane >> 4;                       // k-half for A ldmatrix
    const int bNrow = wn * 64 + (lane & 7) + ((lane >> 4) << 3);
    const int bKh   = (lane >> 3) & 1;                 // k-half for B ldmatrix

    float acc[2][8][4];
#pragma unroll
    for (int i = 0; i < 2; i++)
#pragma unroll
        for (int j = 0; j < 8; j++)
#pragma unroll
            for (int q = 0; q < 4; q++) acc[i][j][q] = 0.0f;

#pragma unroll 1
    for (int i = 0; i < nstg; i++) {
        CP_WAIT3();
        __syncthreads();
        const uint32_t base = sb + (uint32_t)(i & 3) * STAGE_BYTES;

#pragma unroll
        for (int ks = 0; ks < 4; ks++) {
            const uint32_t kb_a = ks * 32 + aKh * 16;
            const uint32_t kb_b = ks * 32 + bKh * 16;
            uint32_t a_h[2][4];
#pragma unroll
            for (int mf = 0; mf < 2; mf++) {
                const int m = mArow + mf * 16;
                const uint32_t so = m * 128 + (kb_a ^ ((m & 7) * 16));
                LDSM_X4(a_h[mf], base + so);
            }
#pragma unroll
            for (int nt = 0; nt < 4; nt++) {
                const int n = bNrow + nt * 16;
                const uint32_t so = n * 128 + (kb_b ^ ((n & 7) * 16));
                uint32_t b_h[4];
                LDSM_X4(b_h, base + 16384 + so);
#pragma unroll
                for (int mf = 0; mf < 2; mf++) {
                    MMA16816(acc[mf][nt*2],   a_h[mf], b_h[0], b_h[1]);
                    MMA16816(acc[mf][nt*2+1], a_h[mf], b_h[2], b_h[3]);
                }
            }
        }
        __syncthreads();
        if (i + 4 < nstg) issue(i + 4, base);
    }

    // ---- epilogue ----
    float* Cfz = 0; __half* Chz = 0;
    if (WF32) Cfz = Cf + z * sC;
    if (WHI)  Chz = Ch + z * sC;
    const int r0 = bm + wm * 32 + (lane >> 2);
    const int cb = bn + wn * 64 + 2 * (lane & 3);
#pragma unroll
    for (int mf = 0; mf < 2; mf++) {
#pragma unroll
        for (int nfr = 0; nfr < 8; nfr++) {
            const int col = cb + (nfr >> 1) * 16 + (nfr & 1) * 8;
            float bx = 0.0f, by = 0.0f;
            if (HAS_BIAS) {
                float2 b2 = *(const float2*)(bias + col);
                bx = b2.x; by = b2.y;
            }
#pragma unroll
            for (int hf = 0; hf < 2; hf++) {
                const int row = r0 + mf * 16 + hf * 8;
                float x0 = acc[mf][nfr][hf * 2 + 0] * alpha;
                float x1 = acc[mf][nfr][hf * 2 + 1] * alpha;
                if (HAS_BIAS) { x0 += bx; x1 += by; }
                if (RELU) { x0 = fmaxf(x0, 0.0f); x1 = fmaxf(x1, 0.0f); }
                if (WF32)
                    *(float2*)(Cfz + (size_t)row * ldc + col) = make_float2(x0, x1);
                if (WHI)
                    *(__half2*)(Chz + (size_t)row * ldc + col) = pack_h2(x0, x1);
            }
        }
    }
}

// ---------------- embed + posenc (writes f32 + fp16) ----------------
__global__ __launch_bounds__(256)
void embed_k(const int* __restrict__ idx, const float* __restrict__ emb,
             float* __restrict__ x, __half* __restrict__ xh)
{
    long tok = blockIdx.x;
    int id = idx[tok];
    if (id >= VOCAB) id = 1;
    int n = (int)(tok & (SEQ - 1));
    int t = threadIdx.x;
    int c0 = t * 4;
    float4 e = ((const float4*)(emb + (size_t)id * DMODEL))[t];

    float nf = (float)n;
    float p0 = (float)c0       * (1.0f / (float)DMODEL);
    float p1 = (float)(c0 + 2) * (1.0f / (float)DMODEL);
    float a0 = nf / powf(10000.0f, p0);
    float a1 = nf / powf(10000.0f, p1);
    float s0, co0, s1, co1;
    sincosf(a0, &s0, &co0);
    sincosf(a1, &s1, &co1);

    float4 r;
    r.x = e.x + s0;  r.y = e.y + co0;
    r.z = e.z + s1;  r.w = e.w + co1;
    ((float4*)(x + (size_t)tok * DMODEL))[t] = r;

    __half2* ph = (__half2*)(xh + (size_t)tok * DMODEL);
    ph[t * 2]     = pack_h2(r.x, r.y);
    ph[t * 2 + 1] = pack_h2(r.z, r.w);
}

// ---------------- transpose + convert: f32 [R,C] -> fp16 [C,R] ----------------
__global__ __launch_bounds__(256)
void tconv_k(const float* __restrict__ src, __half* __restrict__ hi, int R, int C)
{
    __shared__ float s[32][33];
    size_t zoff = (size_t)blockIdx.z * R * C;
    src += zoff; hi += zoff;
    int bx = blockIdx.x * 32;
    int by = blockIdx.y * 32;
    int tx = threadIdx.x & 31, ty = threadIdx.x >> 5;
#pragma unroll
    for (int k = 0; k < 4; k++)
        s[ty + k * 8][tx] = src[(size_t)(by + ty + k * 8) * C + bx + tx];
    __syncthreads();
#pragma unroll
    for (int k = 0; k < 4; k++) {
        float v = s[tx][ty + k * 8];
        hi[(size_t)(bx + ty + k * 8) * R + by + tx] = __float2half_rn(v);
    }
}

// ---------------- residual add + layernorm (f32 + fp16 out) ----------------
__global__ __launch_bounds__(256)
void add_ln_k(const float* __restrict__ a, const float* __restrict__ b,
              const float* __restrict__ g, const float* __restrict__ be,
              float* __restrict__ o, __half* __restrict__ oh)
{
    long row = blockIdx.x;
    int t = threadIdx.x;
    float4 x4 = ((const float4*)(a + (size_t)row * DMODEL))[t];
    float4 y4 = ((const float4*)(b + (size_t)row * DMODEL))[t];
    float4 s4;
    s4.x = x4.x + y4.x; s4.y = x4.y + y4.y;
    s4.z = x4.z + y4.z; s4.w = x4.w + y4.w;

    float s = s4.x + s4.y + s4.z + s4.w;
    float q = s4.x * s4.x + s4.y * s4.y + s4.z * s4.z + s4.w * s4.w;
#pragma unroll
    for (int off = 16; off; off >>= 1) {
        s += __shfl_xor_sync(0xffffffffu, s, off);
        q += __shfl_xor_sync(0xffffffffu, q, off);
    }
    __shared__ float ws[8], wq[8];
    if ((t & 31) == 0) { ws[t >> 5] = s; wq[t >> 5] = q; }
    __syncthreads();
    if (t < 32) {
        s = (t < 8) ? ws[t] : 0.0f;
        q = (t < 8) ? wq[t] : 0.0f;
#pragma unroll
        for (int off = 4; off; off >>= 1) {
            s += __shfl_xor_sync(0xffffffffu, s, off);
            q += __shfl_xor_sync(0xffffffffu, q, off);
        }
        if (t == 0) { ws[0] = s; wq[0] = q; }
    }
    __syncthreads();
    float mean = ws[0] * (1.0f / (float)DMODEL);
    float var  = wq[0] * (1.0f / (float)DMODEL) - mean * mean;
    float rstd = rsqrtf(var + 1e-5f);

    float4 g4 = ((const float4*)g)[t];
    float4 b4 = ((const float4*)be)[t];
    float4 r;
    r.x = (s4.x - mean) * rstd * g4.x + b4.x;
    r.y = (s4.y - mean) * rstd * g4.y + b4.y;
    r.z = (s4.z - mean) * rstd * g4.z + b4.z;
    r.w = (s4.w - mean) * rstd * g4.w + b4.w;
    ((float4*)(o + (size_t)row * DMODEL))[t] = r;

    __half2* ph = (__half2*)(oh + (size_t)row * DMODEL);
    ph[t * 2]     = pack_h2(r.x, r.y);
    ph[t * 2 + 1] = pack_h2(r.z, r.w);
}

// ---------------- head: t3@W4 + b4 -> LN(75) -> sigmoid ----------------
__global__ __launch_bounds__(128)
void head_k(const float* __restrict__ t3, const float* __restrict__ W4,
            const float* __restrict__ b4, const float* __restrict__ g3,
            const float* __restrict__ be3, float* __restrict__ out)
{
    long row = blockIdx.x;
    int t = threadIdx.x;
    __shared__ float r[D3];
    ((float4*)r)[t] = ((const float4*)(t3 + (size_t)row * D3))[t];
    __syncthreads();

    __shared__ float vals[NCAT];
    if (t < NCAT) {
        float acc = b4[t];
#pragma unroll 8
        for (int k = 0; k < D3; k++)
            acc = fmaf(r[k], W4[k * NCAT + t], acc);
        vals[t] = acc;
    }
    __syncthreads();

    __shared__ float stat[2];
    if (t == 0) {
        float s = 0.0f;
        for (int i = 0; i < NCAT; i++) s += vals[i];
        float mean = s * (1.0f / (float)NCAT);
        float q = 0.0f;
        for (int i = 0; i < NCAT; i++) { float d = vals[i] - mean; q += d * d; }
        stat[0] = mean;
        stat[1] = rsqrtf(q * (1.0f / (float)NCAT) + 1e-5f);
    }
    __syncthreads();
    if (t < NCAT) {
        float v = (vals[t] - stat[0]) * stat[1] * g3[t] + be3[t];
        out[(size_t)row * NCAT + t] = 1.0f / (1.0f + expf(-v));
    }
}

// ---------------- launch ----------------
extern "C" void kernel_launch(void* const* d_in, const int* in_sizes, int n_in,
                              void* d_out, int out_size)
{
    const int*   idx = (const int*)  d_in[0];
    const float* emb = (const float*)d_in[1];
    const float* Wq  = (const float*)d_in[2];
    const float* bq  = (const float*)d_in[3];
    const float* Wk  = (const float*)d_in[4];
    const float* bk  = (const float*)d_in[5];
    const float* Wv  = (const float*)d_in[6];
    const float* bv  = (const float*)d_in[7];
    const float* Wu  = (const float*)d_in[8];
    const float* bu  = (const float*)d_in[9];
    const float* g1  = (const float*)d_in[10];
    const float* be1 = (const float*)d_in[11];
    const float* W1  = (const float*)d_in[12];
    const float* b1  = (const float*)d_in[13];
    const float* W2  = (const float*)d_in[14];
    const float* b2  = (const float*)d_in[15];
    const float* g2  = (const float*)d_in[16];
    const float* be2 = (const float*)d_in[17];
    const float* W3  = (const float*)d_in[18];
    const float* b3  = (const float*)d_in[19];
    const float* W4  = (const float*)d_in[20];
    const float* b4  = (const float*)d_in[21];
    const float* g3  = (const float*)d_in[22];
    const float* be3 = (const float*)d_in[23];
    float* out = (float*)d_out;

    unsigned char* ar = nullptr;
    cudaGetSymbolAddress((void**)&ar, g_arena);

    float* X_F   = (float*)(ar + OFF_X_F);
    float* K_F   = (float*)(ar + OFF_K_F);
    float* V_F   = (float*)(ar + OFF_V_F);
    float* U_F   = (float*)(ar + OFF_U_F);
    float* H1_F  = (float*)(ar + OFF_H1_F);
    float* FFO_F = (float*)(ar + OFF_FFO_F);
    float* H2_F  = (float*)(ar + OFF_H2_F);
    float* T3_F  = (float*)(ar + OFF_T3_F);
    __half* XH  = (__half*)(ar + OFF_XH);
    __half* QH  = (__half*)(ar + OFF_QH);
    __half* KTH = (__half*)(ar + OFF_KTH);
    __half* VTH = (__half*)(ar + OFF_VTH);
    __half* KVH = (__half*)(ar + OFF_KVH);
    __half* AH  = (__half*)(ar + OFF_AH);
    __half* H1H = (__half*)(ar + OFF_H1H);
    __half* FBH = (__half*)(ar + OFF_FBH);
    __half* H2H = (__half*)(ar + OFF_H2H);
    __half* WQTH = (__half*)(ar + OFF_WQTH);
    __half* WKTH = (__half*)(ar + OFF_WKTH);
    __half* WVTH = (__half*)(ar + OFF_WVTH);
    __half* WUTH = (__half*)(ar + OFF_WUTH);
    __half* W1TH = (__half*)(ar + OFF_W1TH);
    __half* W2TH = (__half*)(ar + OFF_W2TH);
    __half* W3TH = (__half*)(ar + OFF_W3TH);

    cudaFuncSetAttribute((const void*)gemm_mma<0,1,0,1>, cudaFuncAttributeMaxDynamicSharedMemorySize, GSMEM_BYTES);
    cudaFuncSetAttribute((const void*)gemm_mma<0,1,1,0>, cudaFuncAttributeMaxDynamicSharedMemorySize, GSMEM_BYTES);
    cudaFuncSetAttribute((const void*)gemm_mma<0,0,0,1>, cudaFuncAttributeMaxDynamicSharedMemorySize, GSMEM_BYTES);
    cudaFuncSetAttribute((const void*)gemm_mma<1,1,0,1>, cudaFuncAttributeMaxDynamicSharedMemorySize, GSMEM_BYTES);
    cudaFuncSetAttribute((const void*)gemm_mma<1,1,1,0>, cudaFuncAttributeMaxDynamicSharedMemorySize, GSMEM_BYTES);

    // 1. embedding + posenc
    embed_k<<<TOK, 256>>>(idx, emb, X_F, XH);

    // 2. weight transpose + fp16
    tconv_k<<<dim3(32, 32, 1), 256>>>(Wq, WQTH, DMODEL, DMODEL);
    tconv_k<<<dim3(32, 32, 1), 256>>>(Wk, WKTH, DMODEL, DMODEL);
    tconv_k<<<dim3(32, 32, 1), 256>>>(Wv, WVTH, DMODEL, DMODEL);
    tconv_k<<<dim3(32, 32, 1), 256>>>(Wu, WUTH, DMODEL, DMODEL);
    tconv_k<<<dim3(128, 32, 1), 256>>>(W1, W1TH, DMODEL, FFDIM);
    tconv_k<<<dim3(32, 128, 1), 256>>>(W2, W2TH, FFDIM, DMODEL);
    tconv_k<<<dim3(16, 32, 1), 256>>>(W3, W3TH, DMODEL, D3);

    // 3. projections: Q = fp16; K,V = f32 (then transposed)
    dim3 gp(DMODEL / BN, TOK / BM, 1);
    gemm_mma<0,1,0,1><<<gp, 256, GSMEM_BYTES>>>(XH, WQTH, bq,
        nullptr, QH, DMODEL, DMODEL, 1.0f, 0, 0, 0);
    gemm_mma<0,1,1,0><<<gp, 256, GSMEM_BYTES>>>(XH, WKTH, bk,
        K_F, nullptr, DMODEL, DMODEL, 1.0f, 0, 0, 0);
    gemm_mma<0,1,1,0><<<gp, 256, GSMEM_BYTES>>>(XH, WVTH, bv,
        V_F, nullptr, DMODEL, DMODEL, 1.0f, 0, 0, 0);

    // 4. transpose K, V per batch
    tconv_k<<<dim3(32, 64, BATCH), 256>>>(K_F, KTH, SEQ, DMODEL);
    tconv_k<<<dim3(32, 64, BATCH), 256>>>(V_F, VTH, SEQ, DMODEL);

    // 5. KVt = (V^T K) / 8
    dim3 gkv(DMODEL / BN, DMODEL / BM, BATCH);
    gemm_mma<0,0,0,1><<<gkv, 256, GSMEM_BYTES>>>(VTH, KTH, nullptr,
        nullptr, KVH, SEQ, DMODEL, 0.125f,
        (long long)DMODEL * SEQ, (long long)DMODEL * SEQ, (long long)DMODEL * DMODEL);

    // 6. attn = Q @ KV
    dim3 gat(DMODEL / BN, SEQ / BM, BATCH);
    gemm_mma<0,0,0,1><<<gat, 256, GSMEM_BYTES>>>(QH, KVH, nullptr,
        nullptr, AH, DMODEL, DMODEL, 1.0f,
        (long long)SEQ * DMODEL, (long long)DMODEL * DMODEL, (long long)SEQ * DMODEL);

    // 7. u = attn @ Wu + bu  (f32)
    gemm_mma<0,1,1,0><<<gp, 256, GSMEM_BYTES>>>(AH, WUTH, bu,
        U_F, nullptr, DMODEL, DMODEL, 1.0f, 0, 0, 0);

    // 8. h1 = LN(x + u)
    add_ln_k<<<TOK, 256>>>(X_F, U_F, g1, be1, H1_F, H1H);

    // 9. ff = relu(h1 @ W1 + b1)  (fp16)
    dim3 gf1(FFDIM / BN, TOK / BM, 1);
    gemm_mma<1,1,0,1><<<gf1, 256, GSMEM_BYTES>>>(H1H, W1TH, b1,
        nullptr, FBH, DMODEL, FFDIM, 1.0f, 0, 0, 0);

    // 10. ffo = ff @ W2 + b2  (f32)
    gemm_mma<0,1,1,0><<<gp, 256, GSMEM_BYTES>>>(FBH, W2TH, b2,
        FFO_F, nullptr, FFDIM, DMODEL, 1.0f, 0, 0, 0);

    // 11. h2 = LN(h1 + ffo)
    add_ln_k<<<TOK, 256>>>(H1_F, FFO_F, g2, be2, H2_F, H2H);

    // 12. t3 = relu(h2 @ W3 + b3)  (f32)
    dim3 g3g(D3 / BN, TOK / BM, 1);
    gemm_mma<1,1,1,0><<<g3g, 256, GSMEM_BYTES>>>(H2H, W3TH, b3,
        T3_F, nullptr, DMODEL, D3, 1.0f, 0, 0, 0);

    // 13. out
    head_k<<<TOK, 128>>>(T3_F, W4, b4, g3, be3, out);

    (void)in_sizes; (void)n_in; (void)out_size;
}

// round 17
// speedup vs baseline: 2.3385x; 1.1342x over previous
#include <cuda_runtime.h>
#include <cuda_fp16.h>
#include <math.h>
#include <stdint.h>

// ---------------- problem constants ----------------
#define BATCH   8
#define SEQ     2048
#define DMODEL  1024
#define FFDIM   4096
#define NCAT    75
#define NPAD    128
#define D3      512
#define VOCAB   32000
#define TOK     (BATCH*SEQ)    // 16384

// ---------------- arena ----------------
#define MB (1ull<<20)
#define OFF_X_F    (0ull*MB)     // [16384,1024] f32
#define OFF_U_F    (192ull*MB)
#define OFF_H1_F   (256ull*MB)
#define OFF_FFO_F  (320ull*MB)
#define OFF_H2_F   (384ull*MB)
#define OFF_T3H    (448ull*MB)   // fp16 [16384,512]
#define OFF_LOGI   (456ull*MB)   // f32 [16384,128]
#define OFF_W4T    (466ull*MB)   // fp16 [128,512]
#define OFF_XH     (480ull*MB)   // fp16 [16384,1024]
#define OFF_QH     (544ull*MB)
#define OFF_KTH    (608ull*MB)   // fp16 [8][1024,2048]
#define OFF_VTH    (672ull*MB)
#define OFF_KVH    (736ull*MB)   // fp16 [8][1024,1024]
#define OFF_AH     (768ull*MB)
#define OFF_H1H    (832ull*MB)
#define OFF_FBH    (896ull*MB)   // fp16 [16384,4096]
#define OFF_H2H    (1152ull*MB)
#define OFF_WQTH   (1216ull*MB)
#define OFF_WKTH   (1220ull*MB)
#define OFF_WVTH   (1224ull*MB)
#define OFF_WUTH   (1228ull*MB)
#define OFF_W1TH   (1232ull*MB)  // [4096,1024] fp16
#define OFF_W2TH   (1248ull*MB)  // [1024,4096] fp16
#define OFF_W3TH   (1264ull*MB)  // [512,1024] fp16
#define ARENA_BYTES (1266ull*MB)

__device__ __align__(1024) unsigned char g_arena[ARENA_BYTES];

// ---------------- PTX helpers ----------------
__device__ __forceinline__ uint32_t smem_u32(const void* p) {
    uint32_t a;
    asm("{ .reg .u64 t; cvta.to.shared.u64 t, %1; cvt.u32.u64 %0, t; }" : "=r"(a) : "l"(p));
    return a;
}
__device__ __forceinline__ void cp16(uint32_t s, const void* g) {
    asm volatile("cp.async.cg.shared.global [%0], [%1], 16;" :: "r"(s), "l"(g));
}
#define CP_COMMIT() asm volatile("cp.async.commit_group;" ::: "memory")
#define CP_WAIT3()  asm volatile("cp.async.wait_group 3;"  ::: "memory")

#define LDSM_X4(R, addr) \
    asm volatile("ldmatrix.sync.aligned.m8n8.x4.shared.b16 {%0,%1,%2,%3}, [%4];" \
        : "=r"((R)[0]), "=r"((R)[1]), "=r"((R)[2]), "=r"((R)[3]) : "r"(addr))

#define MMA16816(ac, A, B0, B1) \
    asm volatile("mma.sync.aligned.m16n8k16.row.col.f32.f16.f16.f32 " \
        "{%0,%1,%2,%3},{%4,%5,%6,%7},{%8,%9},{%0,%1,%2,%3};" \
        : "+f"((ac)[0]), "+f"((ac)[1]), "+f"((ac)[2]), "+f"((ac)[3]) \
        : "r"((A)[0]), "r"((A)[1]), "r"((A)[2]), "r"((A)[3]), "r"(B0), "r"(B1))

__device__ __forceinline__ __half2 pack_h2(float a, float b) {
    return __halves2half2(__float2half_rn(a), __float2half_rn(b));
}

// ---------------- fp16 mma.sync GEMM ----------------
// C[M,N] = alpha * (Ah @ Bh^T) (+bias) (opt relu)
// BIAS: 0=none, 1=per-column (bias[col]), 2=per-row (bias[row])
// Tile: BM=128, BN=128, BK=64. 8 warps = 4(m) x 2(n), warp tile 32x64.
// 4-stage cp.async pipeline (4 x 32KB). SW128 swizzle: off ^ ((off>>3)&0x70).
#define BM 128
#define BN 128
#define BK 64
#define STAGE_BYTES 32768      // Ah 16K | Bh 16K
#define NSTAGE 4
#define GSMEM_BYTES (NSTAGE*STAGE_BYTES)

template<int RELU, int BIAS, int WF32, int WHI>
__global__ __launch_bounds__(256)
void gemm_mma(const __half* __restrict__ Ah, const __half* __restrict__ Bh,
              const float* __restrict__ bias,
              float* __restrict__ Cf, __half* __restrict__ Ch,
              int Kd, int ldc, float alpha,
              long long sA, long long sB, long long sC)
{
    extern __shared__ char smc[];
    const int tid  = threadIdx.x;
    const int wid  = tid >> 5;
    const int lane = tid & 31;
    const int bm   = blockIdx.y * BM;
    const int bn   = blockIdx.x * BN;
    const size_t z = blockIdx.z;

    const char* gAh = (const char*)(Ah + z * sA + (size_t)bm * Kd);
    const char* gBh = (const char*)(Bh + z * sB + (size_t)bn * Kd);

    const uint32_t sb = smem_u32(smc);
    const size_t Kb = (size_t)Kd * 2;      // row stride in bytes

    const int ck = tid & 7;  // k-chunk (16B) within row

    auto issue = [&](int s, uint32_t sbase) {
        const size_t kof = (size_t)s * (BK * 2) + (size_t)ck * 16;
#pragma unroll
        for (int j = 0; j < 4; j++) {
            const int row = (tid + j * 256) >> 3;
            const size_t go = (size_t)row * Kb + kof;
            const uint32_t so = row * 128 + ((ck * 16) ^ ((row & 7) * 16));
            cp16(sbase + so,         gAh + go);
            cp16(sbase + 16384 + so, gBh + go);
        }
        CP_COMMIT();
    };

    const int nstg = Kd / BK;
    issue(0, sb);
    issue(1, sb + STAGE_BYTES);
    issue(2, sb + 2 * STAGE_BYTES);
    issue(3, sb + 3 * STAGE_BYTES);

    const int wm = wid & 3, wn = wid >> 2;
    const int mArow = wm * 32 + (lane & 15);
    const int aKh   = lane >> 4;                       // k-half for A ldmatrix
    const int bNrow = wn * 64 + (lane & 7) + ((lane >> 4) << 3);
    const int bKh   = (lane >> 3) & 1;                 // k-half for B ldmatrix

    float acc[2][8][4];
#pragma unroll
    for (int i = 0; i < 2; i++)
#pragma unroll
        for (int j = 0; j < 8; j++)
#pragma unroll
            for (int q = 0; q < 4; q++) acc[i][j][q] = 0.0f;

#pragma unroll 1
    for (int i = 0; i < nstg; i++) {
        CP_WAIT3();
        __syncthreads();
        const uint32_t base = sb + (uint32_t)(i & 3) * STAGE_BYTES;

#pragma unroll
        for (int ks = 0; ks < 4; ks++) {
            const uint32_t kb_a = ks * 32 + aKh * 16;
            const uint32_t kb_b = ks * 32 + bKh * 16;
            uint32_t a_h[2][4];
#pragma unroll
            for (int mf = 0; mf < 2; mf++) {
                const int m = mArow + mf * 16;
                const uint32_t so = m * 128 + (kb_a ^ ((m & 7) * 16));
                LDSM_X4(a_h[mf], base + so);
            }
#pragma unroll
            for (int nt = 0; nt < 4; nt++) {
                const int n = bNrow + nt * 16;
                const uint32_t so = n * 128 + (kb_b ^ ((n & 7) * 16));
                uint32_t b_h[4];
                LDSM_X4(b_h, base + 16384 + so);
#pragma unroll
                for (int mf = 0; mf < 2; mf++) {
                    MMA16816(acc[mf][nt*2],   a_h[mf], b_h[0], b_h[1]);
                    MMA16816(acc[mf][nt*2+1], a_h[mf], b_h[2], b_h[3]);
                }
            }
        }
        __syncthreads();
        if (i + 4 < nstg) issue(i + 4, base);
    }

    // ---- epilogue ----
    float* Cfz = 0; __half* Chz = 0;
    if (WF32) Cfz = Cf + z * sC;
    if (WHI)  Chz = Ch + z * sC;
    const int r0 = bm + wm * 32 + (lane >> 2);
    const int cb = bn + wn * 64 + 2 * (lane & 3);
#pragma unroll
    for (int mf = 0; mf < 2; mf++) {
#pragma unroll
        for (int nfr = 0; nfr < 8; nfr++) {
            const int col = cb + (nfr >> 1) * 16 + (nfr & 1) * 8;
            float bx = 0.0f, by = 0.0f;
            if (BIAS == 1) {
                float2 b2 = *(const float2*)(bias + col);
                bx = b2.x; by = b2.y;
            }
#pragma unroll
            for (int hf = 0; hf < 2; hf++) {
                const int row = r0 + mf * 16 + hf * 8;
                float x0 = acc[mf][nfr][hf * 2 + 0] * alpha;
                float x1 = acc[mf][nfr][hf * 2 + 1] * alpha;
                if (BIAS == 1) { x0 += bx; x1 += by; }
                if (BIAS == 2) {
                    float br = __ldg(bias + row);
                    x0 += br; x1 += br;
                }
                if (RELU) { x0 = fmaxf(x0, 0.0f); x1 = fmaxf(x1, 0.0f); }
                if (WF32)
                    *(float2*)(Cfz + (size_t)row * ldc + col) = make_float2(x0, x1);
                if (WHI)
                    *(__half2*)(Chz + (size_t)row * ldc + col) = pack_h2(x0, x1);
            }
        }
    }
}

// ---------------- embed + posenc (writes f32 + fp16) ----------------
__global__ __launch_bounds__(256)
void embed_k(const int* __restrict__ idx, const float* __restrict__ emb,
             float* __restrict__ x, __half* __restrict__ xh)
{
    long tok = blockIdx.x;
    int id = idx[tok];
    if (id >= VOCAB) id = 1;
    int n = (int)(tok & (SEQ - 1));
    int t = threadIdx.x;
    int c0 = t * 4;
    float4 e = ((const float4*)(emb + (size_t)id * DMODEL))[t];

    float nf = (float)n;
    float p0 = (float)c0       * (1.0f / (float)DMODEL);
    float p1 = (float)(c0 + 2) * (1.0f / (float)DMODEL);
    float a0 = nf / powf(10000.0f, p0);
    float a1 = nf / powf(10000.0f, p1);
    float s0, co0, s1, co1;
    sincosf(a0, &s0, &co0);
    sincosf(a1, &s1, &co1);

    float4 r;
    r.x = e.x + s0;  r.y = e.y + co0;
    r.z = e.z + s1;  r.w = e.w + co1;
    ((float4*)(x + (size_t)tok * DMODEL))[t] = r;

    __half2* ph = (__half2*)(xh + (size_t)tok * DMODEL);
    ph[t * 2]     = pack_h2(r.x, r.y);
    ph[t * 2 + 1] = pack_h2(r.z, r.w);
}

// ---------------- transpose + convert: f32 [R,C] -> fp16 [C,R] ----------------
__global__ __launch_bounds__(256)
void tconv_k(const float* __restrict__ src, __half* __restrict__ hi, int R, int C)
{
    __shared__ float s[32][33];
    size_t zoff = (size_t)blockIdx.z * R * C;
    src += zoff; hi += zoff;
    int bx = blockIdx.x * 32;
    int by = blockIdx.y * 32;
    int tx = threadIdx.x & 31, ty = threadIdx.x >> 5;
#pragma unroll
    for (int k = 0; k < 4; k++)
        s[ty + k * 8][tx] = src[(size_t)(by + ty + k * 8) * C + bx + tx];
    __syncthreads();
#pragma unroll
    for (int k = 0; k < 4; k++) {
        float v = s[tx][ty + k * 8];
        hi[(size_t)(bx + ty + k * 8) * R + by + tx] = __float2half_rn(v);
    }
}

// ---------------- W4 [D3, NCAT] f32 -> W4T [NPAD, D3] fp16 (zero-padded) ----------------
__global__ __launch_bounds__(512)
void w4t_k(const float* __restrict__ W4, __half* __restrict__ W4T)
{
    int k = threadIdx.x;              // 0..511 (D3)
    int n = blockIdx.x;               // 0..127
    float v = (n < NCAT) ? W4[(size_t)k * NCAT + n] : 0.0f;
    W4T[(size_t)n * D3 + k] = __float2half_rn(v);
}

// ---------------- residual add + layernorm (f32 + fp16 out) ----------------
__global__ __launch_bounds__(256)
void add_ln_k(const float* __restrict__ a, const float* __restrict__ b,
              const float* __restrict__ g, const float* __restrict__ be,
              float* __restrict__ o, __half* __restrict__ oh)
{
    long row = blockIdx.x;
    int t = threadIdx.x;
    float4 x4 = ((const float4*)(a + (size_t)row * DMODEL))[t];
    float4 y4 = ((const float4*)(b + (size_t)row * DMODEL))[t];
    float4 s4;
    s4.x = x4.x + y4.x; s4.y = x4.y + y4.y;
    s4.z = x4.z + y4.z; s4.w = x4.w + y4.w;

    float s = s4.x + s4.y + s4.z + s4.w;
    float q = s4.x * s4.x + s4.y * s4.y + s4.z * s4.z + s4.w * s4.w;
#pragma unroll
    for (int off = 16; off; off >>= 1) {
        s += __shfl_xor_sync(0xffffffffu, s, off);
        q += __shfl_xor_sync(0xffffffffu, q, off);
    }
    __shared__ float ws[8], wq[8];
    if ((t & 31) == 0) { ws[t >> 5] = s; wq[t >> 5] = q; }
    __syncthreads();
    if (t < 32) {
        s = (t < 8) ? ws[t] : 0.0f;
        q = (t < 8) ? wq[t] : 0.0f;
#pragma unroll
        for (int off = 4; off; off >>= 1) {
            s += __shfl_xor_sync(0xffffffffu, s, off);
            q += __shfl_xor_sync(0xffffffffu, q, off);
        }
        if (t == 0) { ws[0] = s; wq[0] = q; }
    }
    __syncthreads();
    float mean = ws[0] * (1.0f / (float)DMODEL);
    float var  = wq[0] * (1.0f / (float)DMODEL) - mean * mean;
    float rstd = rsqrtf(var + 1e-5f);

    float4 g4 = ((const float4*)g)[t];
    float4 b4 = ((const float4*)be)[t];
    float4 r;
    r.x = (s4.x - mean) * rstd * g4.x + b4.x;
    r.y = (s4.y - mean) * rstd * g4.y + b4.y;
    r.z = (s4.z - mean) * rstd * g4.z + b4.z;
    r.w = (s4.w - mean) * rstd * g4.w + b4.w;
    ((float4*)(o + (size_t)row * DMODEL))[t] = r;

    __half2* ph = (__half2*)(oh + (size_t)row * DMODEL);
    ph[t * 2]     = pack_h2(r.x, r.y);
    ph[t * 2 + 1] = pack_h2(r.z, r.w);
}

// ---------------- final: +b4 -> LN(75) -> sigmoid (warp per row) ----------------
__global__ __launch_bounds__(128)
void ln75_k(const float* __restrict__ logi, const float* __restrict__ b4,
            const float* __restrict__ g3, const float* __restrict__ be3,
            float* __restrict__ out)
{
    const int w    = threadIdx.x >> 5;
    const int lane = threadIdx.x & 31;
    const long row = (long)blockIdx.x * 4 + w;
    const float* src = logi + (size_t)row * NPAD;

    float v[3]; int c[3];
    float s = 0.0f, q = 0.0f;
#pragma unroll
    for (int j = 0; j < 3; j++) {
        c[j] = lane + j * 32;
        v[j] = 0.0f;
        if (c[j] < NCAT) {
            v[j] = src[c[j]] + __ldg(b4 + c[j]);
            s += v[j];
            q += v[j] * v[j];
        }
    }
#pragma unroll
    for (int off = 16; off; off >>= 1) {
        s += __shfl_xor_sync(0xffffffffu, s, off);
        q += __shfl_xor_sync(0xffffffffu, q, off);
    }
    const float mean = s * (1.0f / (float)NCAT);
    const float var  = q * (1.0f / (float)NCAT) - mean * mean;
    const float rstd = rsqrtf(var + 1e-5f);
#pragma unroll
    for (int j = 0; j < 3; j++) {
        if (c[j] < NCAT) {
            float x = (v[j] - mean) * rstd * __ldg(g3 + c[j]) + __ldg(be3 + c[j]);
            out[(size_t)row * NCAT + c[j]] = 1.0f / (1.0f + expf(-x));
        }
    }
}

// ---------------- launch ----------------
extern "C" void kernel_launch(void* const* d_in, const int* in_sizes, int n_in,
                              void* d_out, int out_size)
{
    const int*   idx = (const int*)  d_in[0];
    const float* emb = (const float*)d_in[1];
    const float* Wq  = (const float*)d_in[2];
    const float* bq  = (const float*)d_in[3];
    const float* Wk  = (const float*)d_in[4];
    const float* bk  = (const float*)d_in[5];
    const float* Wv  = (const float*)d_in[6];
    const float* bv  = (const float*)d_in[7];
    const float* Wu  = (const float*)d_in[8];
    const float* bu  = (const float*)d_in[9];
    const float* g1  = (const float*)d_in[10];
    const float* be1 = (const float*)d_in[11];
    const float* W1  = (const float*)d_in[12];
    const float* b1  = (const float*)d_in[13];
    const float* W2  = (const float*)d_in[14];
    const float* b2  = (const float*)d_in[15];
    const float* g2  = (const float*)d_in[16];
    const float* be2 = (const float*)d_in[17];
    const float* W3  = (const float*)d_in[18];
    const float* b3  = (const float*)d_in[19];
    const float* W4  = (const float*)d_in[20];
    const float* b4  = (const float*)d_in[21];
    const float* g3  = (const float*)d_in[22];
    const float* be3 = (const float*)d_in[23];
    float* out = (float*)d_out;

    unsigned char* ar = nullptr;
    cudaGetSymbolAddress((void**)&ar, g_arena);

    float* X_F   = (float*)(ar + OFF_X_F);
    float* U_F   = (float*)(ar + OFF_U_F);
    float* H1_F  = (float*)(ar + OFF_H1_F);
    float* FFO_F = (float*)(ar + OFF_FFO_F);
    float* H2_F  = (float*)(ar + OFF_H2_F);
    float* LOGI  = (float*)(ar + OFF_LOGI);
    __half* T3H = (__half*)(ar + OFF_T3H);
    __half* W4T = (__half*)(ar + OFF_W4T);
    __half* XH  = (__half*)(ar + OFF_XH);
    __half* QH  = (__half*)(ar + OFF_QH);
    __half* KTH = (__half*)(ar + OFF_KTH);
    __half* VTH = (__half*)(ar + OFF_VTH);
    __half* KVH = (__half*)(ar + OFF_KVH);
    __half* AH  = (__half*)(ar + OFF_AH);
    __half* H1H = (__half*)(ar + OFF_H1H);
    __half* FBH = (__half*)(ar + OFF_FBH);
    __half* H2H = (__half*)(ar + OFF_H2H);
    __half* WQTH = (__half*)(ar + OFF_WQTH);
    __half* WKTH = (__half*)(ar + OFF_WKTH);
    __half* WVTH = (__half*)(ar + OFF_WVTH);
    __half* WUTH = (__half*)(ar + OFF_WUTH);
    __half* W1TH = (__half*)(ar + OFF_W1TH);
    __half* W2TH = (__half*)(ar + OFF_W2TH);
    __half* W3TH = (__half*)(ar + OFF_W3TH);

    cudaFuncSetAttribute((const void*)gemm_mma<0,1,0,1>, cudaFuncAttributeMaxDynamicSharedMemorySize, GSMEM_BYTES);
    cudaFuncSetAttribute((const void*)gemm_mma<0,2,0,1>, cudaFuncAttributeMaxDynamicSharedMemorySize, GSMEM_BYTES);
    cudaFuncSetAttribute((const void*)gemm_mma<0,0,0,1>, cudaFuncAttributeMaxDynamicSharedMemorySize, GSMEM_BYTES);
    cudaFuncSetAttribute((const void*)gemm_mma<0,1,1,0>, cudaFuncAttributeMaxDynamicSharedMemorySize, GSMEM_BYTES);
    cudaFuncSetAttribute((const void*)gemm_mma<1,1,0,1>, cudaFuncAttributeMaxDynamicSharedMemorySize, GSMEM_BYTES);
    cudaFuncSetAttribute((const void*)gemm_mma<0,0,1,0>, cudaFuncAttributeMaxDynamicSharedMemorySize, GSMEM_BYTES);

    // 1. embedding + posenc
    embed_k<<<TOK, 256>>>(idx, emb, X_F, XH);

    // 2. weight transpose + fp16 (+ padded W4T)
    tconv_k<<<dim3(32, 32, 1), 256>>>(Wq, WQTH, DMODEL, DMODEL);
    tconv_k<<<dim3(32, 32, 1), 256>>>(Wk, WKTH, DMODEL, DMODEL);
    tconv_k<<<dim3(32, 32, 1), 256>>>(Wv, WVTH, DMODEL, DMODEL);
    tconv_k<<<dim3(32, 32, 1), 256>>>(Wu, WUTH, DMODEL, DMODEL);
    tconv_k<<<dim3(128, 32, 1), 256>>>(W1, W1TH, DMODEL, FFDIM);
    tconv_k<<<dim3(32, 128, 1), 256>>>(W2, W2TH, FFDIM, DMODEL);
    tconv_k<<<dim3(16, 32, 1), 256>>>(W3, W3TH, DMODEL, D3);
    w4t_k<<<NPAD, D3>>>(W4, W4T);

    // 3a. Q = X @ Wq + bq  (normal orientation, fp16)
    dim3 gp(DMODEL / BN, TOK / BM, 1);
    gemm_mma<0,1,0,1><<<gp, 256, GSMEM_BYTES>>>(XH, WQTH, bq,
        nullptr, QH, DMODEL, DMODEL, 1.0f, 0, 0, 0);

    // 3b. KT = Wk^T @ X^T + bk  (transposed directly: A=WkT, B=X per batch, bias per-row)
    dim3 gkt(SEQ / BN, DMODEL / BM, BATCH);
    gemm_mma<0,2,0,1><<<gkt, 256, GSMEM_BYTES>>>(WKTH, XH, bk,
        nullptr, KTH, DMODEL, SEQ, 1.0f,
        0, (long long)SEQ * DMODEL, (long long)DMODEL * SEQ);
    gemm_mma<0,2,0,1><<<gkt, 256, GSMEM_BYTES>>>(WVTH, XH, bv,
        nullptr, VTH, DMODEL, SEQ, 1.0f,
        0, (long long)SEQ * DMODEL, (long long)DMODEL * SEQ);

    // 4. KVt = (V^T K) / 8
    dim3 gkv(DMODEL / BN, DMODEL / BM, BATCH);
    gemm_mma<0,0,0,1><<<gkv, 256, GSMEM_BYTES>>>(VTH, KTH, nullptr,
        nullptr, KVH, SEQ, DMODEL, 0.125f,
        (long long)DMODEL * SEQ, (long long)DMODEL * SEQ, (long long)DMODEL * DMODEL);

    // 5. attn = Q @ KV
    dim3 gat(DMODEL / BN, SEQ / BM, BATCH);
    gemm_mma<0,0,0,1><<<gat, 256, GSMEM_BYTES>>>(QH, KVH, nullptr,
        nullptr, AH, DMODEL, DMODEL, 1.0f,
        (long long)SEQ * DMODEL, (long long)DMODEL * DMODEL, (long long)SEQ * DMODEL);

    // 6. u = attn @ Wu + bu  (f32)
    gemm_mma<0,1,1,0><<<gp, 256, GSMEM_BYTES>>>(AH, WUTH, bu,
        U_F, nullptr, DMODEL, DMODEL, 1.0f, 0, 0, 0);

    // 7. h1 = LN(x + u)
    add_ln_k<<<TOK, 256>>>(X_F, U_F, g1, be1, H1_F, H1H);

    // 8. ff = relu(h1 @ W1 + b1)  (fp16)
    dim3 gf1(FFDIM / BN, TOK / BM, 1);
    gemm_mma<1,1,0,1><<<gf1, 256, GSMEM_BYTES>>>(H1H, W1TH, b1,
        nullptr, FBH, DMODEL, FFDIM, 1.0f, 0, 0, 0);

    // 9. ffo = ff @ W2 + b2  (f32)
    gemm_mma<0,1,1,0><<<gp, 256, GSMEM_BYTES>>>(FBH, W2TH, b2,
        FFO_F, nullptr, FFDIM, DMODEL, 1.0f, 0, 0, 0);

    // 10. h2 = LN(h1 + ffo)
    add_ln_k<<<TOK, 256>>>(H1_F, FFO_F, g2, be2, H2_F, H2H);

    // 11. t3 = relu(h2 @ W3 + b3)  (fp16)
    dim3 g3g(D3 / BN, TOK / BM, 1);
    gemm_mma<1,1,0,1><<<g3g, 256, GSMEM_BYTES>>>(H2H, W3TH, b3,
        nullptr, T3H, DMODEL, D3, 1.0f, 0, 0, 0);

    // 12. logits = t3 @ W4T^T  (f32, N padded to 128; b4 added in ln75)
    dim3 glo(NPAD / BN, TOK / BM, 1);
    gemm_mma<0,0,1,0><<<glo, 256, GSMEM_BYTES>>>(T3H, W4T, nullptr,
        LOGI, nullptr, D3, NPAD, 1.0f, 0, 0, 0);

    // 13. out = sigmoid(LN(logits + b4))
    ln75_k<<<TOK / 4, 128>>>(LOGI, b4, g3, be3, out);

    (void)in_sizes; (void)n_in; (void)out_size;
}